// round 11
// baseline (speedup 1.0000x reference)
#include <cuda_runtime.h>
#include <math.h>
#include <stdint.h>

// Problem constants
#define DIMC   128
#define NWIN   49
#define HEADS  4
#define HD     32
#define NB     4096
#define M_TOTAL (NB * NWIN)        // 200704 = 1568 * 128
#define M_TILES (M_TOTAL / 128)    // 1568

// Scratch (allocation-free rule: static device globals)
__device__ float g_qkv[(size_t)NB * NWIN * 384];   // [M, 384] : q|k|v per row
__device__ float g_att[(size_t)NB * NWIN * DIMC];  // [M, 128] : attention output
__device__ float g_comb[4 * 64 * 49 * 56];         // (bias+mask)*sqrt(hd), [h][wm][i][j]

__device__ __forceinline__ float to_tf32(float x) {
    float r;
    asm("cvt.rna.tf32.f32 %0, %1;" : "=f"(r) : "f"(x));
    return r;
}
// round-to-nearest tf32 as raw bits (tensor core truncates low 13 bits)
__device__ __forceinline__ uint32_t rna_bits(float x) {
    return __float_as_uint(x) + 0x1000u;
}

__device__ __forceinline__ void mma_tf32(float c[4], const uint32_t a[4],
                                         uint32_t b0, uint32_t b1) {
    asm volatile(
        "mma.sync.aligned.m16n8k8.row.col.f32.tf32.tf32.f32 "
        "{%0,%1,%2,%3}, {%4,%5,%6,%7}, {%8,%9}, {%0,%1,%2,%3};"
        : "+f"(c[0]), "+f"(c[1]), "+f"(c[2]), "+f"(c[3])
        : "r"(a[0]), "r"(a[1]), "r"(a[2]), "r"(a[3]), "r"(b0), "r"(b1));
}

#define CP_ASYNC16(dst, src) \
    asm volatile("cp.async.ca.shared.global [%0], [%1], 16;" :: "r"(dst), "l"(src))
#define CP_COMMIT() asm volatile("cp.async.commit_group;")

// ---------------------------------------------------------------------------
// tf32 GEMM v6: C[M][NC] = A[M][128] * W[NC][128]^T + bias
// Same tile/warp layout as the frozen v3 winner (128x128, 8 warps, warp tile
// 64x32), but K-chunk 32 (4 chunks instead of 8): halves the number of
// wait_group + __syncthreads iterations and staging groups. 3-buffer ring,
// row stride 36 floats (== 4 mod 32: fragment LDS.32 conflict-free; rows
// 16B aligned for cp.async). tf32 RNA applied at fragment load.
// ---------------------------------------------------------------------------
#define CHUNK_FLOATS (128 * 36)                 // 4608 floats per buf per array
#define ABUF_BYTES   (CHUNK_FLOATS * 4)         // 18432
#define GEMM_SMEM_BYTES (6 * ABUF_BYTES)        // 110592: 3 bufs x (A + W)

template<int NC>
__device__ __forceinline__ void gemm_tc6_body(
    const float* __restrict__ A, const float* __restrict__ W,
    const float* __restrict__ bias, float* __restrict__ C,
    float* sm, long m0, int n0)
{
    const int tid  = threadIdx.x;
    const int lane = tid & 31;
    const int warp = tid >> 5;
    const int wm   = warp & 1;
    const int wn   = warp >> 1;
    const int g    = lane >> 2;
    const int t    = lane & 3;

    // staging map: thread moves 4 consecutive 16B lines of one row for A
    // and the same for W, per chunk.
    const int srow = tid >> 1;                   // 0..127
    const int sf   = (tid & 1) * 16;             // float offset 0 or 16
    const float* gA = A + (m0 + srow) * 128 + sf;
    const float* gW = W + ((size_t)n0 + srow) * 128 + sf;
    const uint32_t sbase = (uint32_t)__cvta_generic_to_shared(sm);
    const uint32_t sA = sbase + (srow * 36 + sf) * 4;
    const uint32_t sW = sA + 3 * ABUF_BYTES;

    auto stage = [&](int kc) {
        const int buf = kc % 3;
        const float* a = gA + kc * 32;
        const float* w = gW + kc * 32;
        #pragma unroll
        for (int j = 0; j < 4; j++) {
            CP_ASYNC16(sA + buf * ABUF_BYTES + j * 16, a + j * 4);
            CP_ASYNC16(sW + buf * ABUF_BYTES + j * 16, w + j * 4);
        }
    };

    float acc[4][4][4] = {};

    stage(0); CP_COMMIT();
    stage(1); CP_COMMIT();

    #pragma unroll
    for (int kc = 0; kc < 4; kc++) {
        if (kc < 3) asm volatile("cp.async.wait_group 1;");
        else        asm volatile("cp.async.wait_group 0;");
        __syncthreads();
        if (kc < 2) { stage(kc + 2); CP_COMMIT(); }

        const float* Ab = sm + (kc % 3) * CHUNK_FLOATS;
        const float* Wb = Ab + 3 * CHUNK_FLOATS;

        #pragma unroll
        for (int s = 0; s < 4; s++) {
            const int off = s * 8;
            uint32_t a[4][4];
            #pragma unroll
            for (int mt = 0; mt < 4; mt++) {
                int r = wm * 64 + mt * 16 + g;
                a[mt][0] = rna_bits(Ab[r * 36 + off + t]);
                a[mt][1] = rna_bits(Ab[(r + 8) * 36 + off + t]);
                a[mt][2] = rna_bits(Ab[r * 36 + off + t + 4]);
                a[mt][3] = rna_bits(Ab[(r + 8) * 36 + off + t + 4]);
            }
            #pragma unroll
            for (int nt = 0; nt < 4; nt++) {
                int n = wn * 32 + nt * 8 + g;
                uint32_t b0 = rna_bits(Wb[n * 36 + off + t]);
                uint32_t b1 = rna_bits(Wb[n * 36 + off + t + 4]);
                #pragma unroll
                for (int mt = 0; mt < 4; mt++)
                    mma_tf32(acc[mt][nt], a[mt], b0, b1);
            }
        }
    }

    #pragma unroll
    for (int nt = 0; nt < 4; nt++) {
        int col = n0 + wn * 32 + nt * 8 + 2 * t;
        float b0 = bias[col], b1 = bias[col + 1];
        #pragma unroll
        for (int mt = 0; mt < 4; mt++) {
            long r = m0 + wm * 64 + mt * 16 + g;
            *(float2*)&C[r * NC + col] =
                make_float2(acc[mt][nt][0] + b0, acc[mt][nt][1] + b1);
            *(float2*)&C[(r + 8) * NC + col] =
                make_float2(acc[mt][nt][2] + b0, acc[mt][nt][3] + b1);
        }
    }
}

// GEMM3 (proj): plain gemm
template<int NC>
__global__ __launch_bounds__(256, 2) void gemm_tc6_kernel(
    const float* __restrict__ A, const float* __restrict__ W,
    const float* __restrict__ bias, float* __restrict__ C)
{
    extern __shared__ float sm[];
    gemm_tc6_body<NC>(A, W, bias, C, sm, (long)blockIdx.y * 128, blockIdx.x * 128);
}

// GEMM1 + fused precomp: extra grid rows (blockIdx.y >= M_TILES) build
// g_comb[h][wm][i][j(pad56)] = (bias + mask) * sqrt(hd); pad cols -1e30.
__global__ __launch_bounds__(256, 2) void gemm1_precomp_kernel(
    const float* __restrict__ A, const float* __restrict__ W,
    const float* __restrict__ bias, float* __restrict__ C,
    const float* __restrict__ mask, const float* __restrict__ bias_table,
    const int* __restrict__ rel_index)
{
    extern __shared__ float sm[];
    if (blockIdx.y >= M_TILES) {
        const int pid = (blockIdx.y - M_TILES) * 3 + blockIdx.x;
        if (pid >= 256) return;
        const int wm = pid & 63, h = pid >> 6;
        const float inv_scale = 5.656854249492381f;  // sqrt(32)
        float* dst = g_comb + ((size_t)h * 64 + wm) * 49 * 56;
        for (int q = threadIdx.x; q < 49 * 56; q += 256) {
            int i = q / 56, j = q - i * 56;
            dst[q] = (j < 49)
                ? (bias_table[rel_index[i * 49 + j] * HEADS + h]
                   + mask[(size_t)wm * (NWIN * NWIN) + i * 49 + j]) * inv_scale
                : -1e30f;
        }
        return;
    }
    gemm_tc6_body<384>(A, W, bias, C, sm, (long)blockIdx.y * 128, blockIdx.x * 128);
}

// ---------------------------------------------------------------------------
// Attention v4 (frozen round-10 winner). Block = (window b, head h), 128 thr.
// ---------------------------------------------------------------------------
__global__ __launch_bounds__(128) void attn_tc_kernel(
    const float* __restrict__ qkv, float* __restrict__ outp)
{
    __shared__ float Qs[64][40];   // rows 49..63 uninit (outputs masked)
    __shared__ float Ks[56][40];   // rows 49..55 zeroed
    __shared__ float Vs[56][40];   // rows 49..55 zeroed
    __shared__ float Ps[64][72];

    const int tid  = threadIdx.x;
    const int lane = tid & 31;
    const int warp = tid >> 5;
    const int g = lane >> 2, t = lane & 3;
    const int b = blockIdx.x >> 2, h = blockIdx.x & 3;
    const float scale = 0.17677669529663687f;   // 32^-0.5

    // ---- cp.async staging of Q, K, V (49 rows x 32 floats each) ----
    {
        const float* base = qkv + ((size_t)b * 49) * 384 + h * 32;
        const uint32_t sQ = (uint32_t)__cvta_generic_to_shared(&Qs[0][0]);
        const uint32_t sK = (uint32_t)__cvta_generic_to_shared(&Ks[0][0]);
        const uint32_t sV = (uint32_t)__cvta_generic_to_shared(&Vs[0][0]);
        for (int q = tid; q < 392; q += 128) {
            int i = q >> 3, seg = q & 7;
            CP_ASYNC16(sQ + (i * 40 + seg * 4) * 4, base + (size_t)i * 384 + seg * 4);
        }
        for (int q = tid; q < 392; q += 128) {
            int i = q >> 3, seg = q & 7;
            CP_ASYNC16(sK + (i * 40 + seg * 4) * 4, base + (size_t)i * 384 + 128 + seg * 4);
        }
        for (int q = tid; q < 392; q += 128) {
            int i = q >> 3, seg = q & 7;
            CP_ASYNC16(sV + (i * 40 + seg * 4) * 4, base + (size_t)i * 384 + 256 + seg * 4);
        }
        CP_COMMIT();
        for (int q = tid; q < 7 * 40; q += 128) {
            int i = 49 + q / 40, c2 = q % 40;
            Ks[i][c2] = 0.f;
            Vs[i][c2] = 0.f;
        }
    }

    // ---- init S accumulators from comb*sqrt(hd) (overlaps with cp.async) ----
    const int r0 = warp * 16 + g;
    const float* comb = g_comb + ((size_t)h * 64 + (b & 63)) * 49 * 56;
    float c[7][4];
    #pragma unroll
    for (int nt = 0; nt < 7; nt++) {
        const int col = nt * 8 + 2 * t;
        if (r0 < 49) {
            float2 f = *(const float2*)&comb[r0 * 56 + col];
            c[nt][0] = f.x; c[nt][1] = f.y;
        } else { c[nt][0] = 0.f; c[nt][1] = 0.f; }
        if (r0 + 8 < 49) {
            float2 f = *(const float2*)&comb[(r0 + 8) * 56 + col];
            c[nt][2] = f.x; c[nt][3] = f.y;
        } else { c[nt][2] = 0.f; c[nt][3] = 0.f; }
    }

    asm volatile("cp.async.wait_group 0;");
    __syncthreads();

    // ---- S' = QK^T + comb*sqrt(hd) ----
    #pragma unroll
    for (int s = 0; s < 4; s++) {
        const int off = s * 8;
        uint32_t a[4];
        a[0] = rna_bits(Qs[r0][off + t]);
        a[1] = rna_bits(Qs[r0 + 8][off + t]);
        a[2] = rna_bits(Qs[r0][off + t + 4]);
        a[3] = rna_bits(Qs[r0 + 8][off + t + 4]);
        #pragma unroll
        for (int nt = 0; nt < 7; nt++) {
            uint32_t b0 = rna_bits(Ks[nt * 8 + g][off + t]);
            uint32_t b1 = rna_bits(Ks[nt * 8 + g][off + t + 4]);
            mma_tf32(c[nt], a, b0, b1);
        }
    }

    // ---- softmax(scale * S') in registers ----
    {
        float mx0 = -1e30f, mx1 = -1e30f;
        #pragma unroll
        for (int nt = 0; nt < 7; nt++) {
            mx0 = fmaxf(mx0, fmaxf(c[nt][0], c[nt][1]));
            mx1 = fmaxf(mx1, fmaxf(c[nt][2], c[nt][3]));
        }
        mx0 = fmaxf(mx0, __shfl_xor_sync(0xffffffffu, mx0, 1));
        mx0 = fmaxf(mx0, __shfl_xor_sync(0xffffffffu, mx0, 2));
        mx1 = fmaxf(mx1, __shfl_xor_sync(0xffffffffu, mx1, 1));
        mx1 = fmaxf(mx1, __shfl_xor_sync(0xffffffffu, mx1, 2));
        float s0 = 0.f, s1 = 0.f;
        #pragma unroll
        for (int nt = 0; nt < 7; nt++) {
            c[nt][0] = __expf((c[nt][0] - mx0) * scale);
            c[nt][1] = __expf((c[nt][1] - mx0) * scale);
            c[nt][2] = __expf((c[nt][2] - mx1) * scale);
            c[nt][3] = __expf((c[nt][3] - mx1) * scale);
            s0 += c[nt][0] + c[nt][1];
            s1 += c[nt][2] + c[nt][3];
        }
        s0 += __shfl_xor_sync(0xffffffffu, s0, 1);
        s0 += __shfl_xor_sync(0xffffffffu, s0, 2);
        s1 += __shfl_xor_sync(0xffffffffu, s1, 1);
        s1 += __shfl_xor_sync(0xffffffffu, s1, 2);
        const float i0 = 1.f / s0, i1 = 1.f / s1;

        #pragma unroll
        for (int nt = 0; nt < 7; nt++) {
            const int col = nt * 8 + 2 * t;
            *(float2*)&Ps[r0][col] =
                make_float2(to_tf32(c[nt][0] * i0), to_tf32(c[nt][1] * i0));
            *(float2*)&Ps[r0 + 8][col] =
                make_float2(to_tf32(c[nt][2] * i1), to_tf32(c[nt][3] * i1));
        }
    }
    __syncwarp();

    // ---- O = P V ----
    float o[4][4];
    #pragma unroll
    for (int nt = 0; nt < 4; nt++)
        #pragma unroll
        for (int e = 0; e < 4; e++) o[nt][e] = 0.f;

    #pragma unroll
    for (int s = 0; s < 7; s++) {
        const int off = s * 8;
        uint32_t a[4];
        a[0] = __float_as_uint(Ps[r0][off + t]);
        a[1] = __float_as_uint(Ps[r0 + 8][off + t]);
        a[2] = __float_as_uint(Ps[r0][off + t + 4]);
        a[3] = __float_as_uint(Ps[r0 + 8][off + t + 4]);
        #pragma unroll
        for (int nt = 0; nt < 4; nt++) {
            uint32_t b0 = rna_bits(Vs[off + t][nt * 8 + g]);
            uint32_t b1 = rna_bits(Vs[off + t + 4][nt * 8 + g]);
            mma_tf32(o[nt], a, b0, b1);
        }
    }

    #pragma unroll
    for (int nt = 0; nt < 4; nt++) {
        const int d = nt * 8 + 2 * t;
        if (r0 < 49)
            *(float2*)&outp[((size_t)b * 49 + r0) * DIMC + h * HD + d]
                = make_float2(o[nt][0], o[nt][1]);
        if (r0 + 8 < 49)
            *(float2*)&outp[((size_t)b * 49 + r0 + 8) * DIMC + h * HD + d]
                = make_float2(o[nt][2], o[nt][3]);
    }
}

// ---------------------------------------------------------------------------
extern "C" void kernel_launch(void* const* d_in, const int* in_sizes, int n_in,
                              void* d_out, int out_size)
{
    const float* x          = (const float*)d_in[0];
    const float* mask       = (const float*)d_in[1];
    const float* qkv_w      = (const float*)d_in[2];
    const float* qkv_b      = (const float*)d_in[3];
    const float* proj_w     = (const float*)d_in[4];
    const float* proj_b     = (const float*)d_in[5];
    const float* bias_table = (const float*)d_in[6];
    const int*   rel_index  = (const int*)d_in[7];
    float*       out        = (float*)d_out;

    float *qkvbuf = nullptr, *attbuf = nullptr;
    cudaGetSymbolAddress((void**)&qkvbuf, g_qkv);
    cudaGetSymbolAddress((void**)&attbuf, g_att);

    cudaFuncSetAttribute(gemm1_precomp_kernel,
                         cudaFuncAttributeMaxDynamicSharedMemorySize, GEMM_SMEM_BYTES);
    cudaFuncSetAttribute(gemm_tc6_kernel<DIMC>,
                         cudaFuncAttributeMaxDynamicSharedMemorySize, GEMM_SMEM_BYTES);

    // GEMM1 with precomp folded in as extra grid rows (86 rows x 3 = 258 blocks)
    dim3 g1(384 / 128, M_TILES + 86);
    gemm1_precomp_kernel<<<g1, 256, GEMM_SMEM_BYTES>>>(
        x, qkv_w, qkv_b, qkvbuf, mask, bias_table, rel_index);

    attn_tc_kernel<<<NB * HEADS, 128>>>(qkvbuf, attbuf);

    dim3 g3(DIMC / 128, M_TILES);
    gemm_tc6_kernel<DIMC><<<g3, 256, GEMM_SMEM_BYTES>>>(attbuf, proj_w, proj_b, out);
}

// round 12
// speedup vs baseline: 1.2706x; 1.2706x over previous
#include <cuda_runtime.h>
#include <math.h>
#include <stdint.h>

// Problem constants
#define DIMC   128
#define NWIN   49
#define HEADS  4
#define HD     32
#define NB     4096
#define M_TOTAL (NB * NWIN)        // 200704 = 1568 * 128
#define M_TILES (M_TOTAL / 128)    // 1568

// Scratch (allocation-free rule: static device globals)
__device__ float g_qkv[(size_t)NB * NWIN * 384];   // [M, 384] : q|k|v per row
__device__ float g_att[(size_t)NB * NWIN * DIMC];  // [M, 128] : attention output
__device__ float g_comb[4 * 64 * 49 * 56];         // (bias+mask)*sqrt(hd), [h][wm][i][j]

__device__ __forceinline__ float to_tf32(float x) {
    float r;
    asm("cvt.rna.tf32.f32 %0, %1;" : "=f"(r) : "f"(x));
    return r;
}
// round-to-nearest tf32 as raw bits (tensor core truncates low 13 bits)
__device__ __forceinline__ uint32_t rna_bits(float x) {
    return __float_as_uint(x) + 0x1000u;
}

__device__ __forceinline__ void mma_tf32(float c[4], const uint32_t a[4],
                                         uint32_t b0, uint32_t b1) {
    asm volatile(
        "mma.sync.aligned.m16n8k8.row.col.f32.tf32.tf32.f32 "
        "{%0,%1,%2,%3}, {%4,%5,%6,%7}, {%8,%9}, {%0,%1,%2,%3};"
        : "+f"(c[0]), "+f"(c[1]), "+f"(c[2]), "+f"(c[3])
        : "r"(a[0]), "r"(a[1]), "r"(a[2]), "r"(a[3]), "r"(b0), "r"(b1));
}

#define CP_ASYNC16(dst, src) \
    asm volatile("cp.async.ca.shared.global [%0], [%1], 16;" :: "r"(dst), "l"(src))
#define CP_COMMIT() asm volatile("cp.async.commit_group;")

// ---------------------------------------------------------------------------
// tf32 GEMM v3 body (frozen winner: 128x128 tile, 8 warps, warp tile 64x32,
// K chunks of 16, stride-20 smem) — now with a 4-stage cp.async ring:
// steady state waits at wait_group 2 (two chunks in flight during compute).
// ---------------------------------------------------------------------------
#define BUFB_ 10240                              // 128*20*4 bytes per array buf
#define GEMM_SMEM_BYTES (8 * BUFB_)              // 4 bufs x (A + W) = 81920

template<int NC>
__device__ __forceinline__ void gemm_tc3_body(
    const float* __restrict__ A, const float* __restrict__ W,
    const float* __restrict__ bias, float* __restrict__ C,
    float* sm, long m0, int n0)
{
    const int tid  = threadIdx.x;
    const int lane = tid & 31;
    const int warp = tid >> 5;
    const int wm   = warp & 1;
    const int wn   = warp >> 1;
    const int g    = lane >> 2;
    const int t    = lane & 3;

    const int srow = tid >> 2;
    const int sf   = tid & 3;
    const float* gA = A + (m0 + srow) * 128 + sf * 4;
    const float* gW = W + ((size_t)n0 + srow) * 128 + sf * 4;
    const uint32_t sbase = (uint32_t)__cvta_generic_to_shared(sm);
    const uint32_t sA = sbase + (srow * 20 + sf * 4) * 4;
    const uint32_t sW = sA + 4 * BUFB_;
    const uint32_t ROW64 = 64 * 20 * 4;

    auto stage = [&](int kc) {
        const int buf = kc & 3;
        const float* a = gA + kc * 16;
        const float* w = gW + kc * 16;
        CP_ASYNC16(sA + buf * BUFB_,         a);
        CP_ASYNC16(sA + buf * BUFB_ + ROW64, a + 64 * 128);
        CP_ASYNC16(sW + buf * BUFB_,         w);
        CP_ASYNC16(sW + buf * BUFB_ + ROW64, w + 64 * 128);
    };

    float acc[4][4][4] = {};

    stage(0); CP_COMMIT();
    stage(1); CP_COMMIT();
    stage(2); CP_COMMIT();

    #pragma unroll
    for (int kc = 0; kc < 8; kc++) {
        if      (kc < 6) asm volatile("cp.async.wait_group 2;");
        else if (kc < 7) asm volatile("cp.async.wait_group 1;");
        else             asm volatile("cp.async.wait_group 0;");
        __syncthreads();
        if (kc < 5) { stage(kc + 3); CP_COMMIT(); }

        const float* Ab = sm + (kc & 3) * 2560;
        const float* Wb = Ab + 4 * 2560;

        #pragma unroll
        for (int s = 0; s < 2; s++) {
            const int off = s * 8;
            uint32_t a[4][4];
            #pragma unroll
            for (int mt = 0; mt < 4; mt++) {
                int r = wm * 64 + mt * 16 + g;
                a[mt][0] = rna_bits(Ab[r * 20 + off + t]);
                a[mt][1] = rna_bits(Ab[(r + 8) * 20 + off + t]);
                a[mt][2] = rna_bits(Ab[r * 20 + off + t + 4]);
                a[mt][3] = rna_bits(Ab[(r + 8) * 20 + off + t + 4]);
            }
            #pragma unroll
            for (int nt = 0; nt < 4; nt++) {
                int n = wn * 32 + nt * 8 + g;
                uint32_t b0 = rna_bits(Wb[n * 20 + off + t]);
                uint32_t b1 = rna_bits(Wb[n * 20 + off + t + 4]);
                #pragma unroll
                for (int mt = 0; mt < 4; mt++)
                    mma_tf32(acc[mt][nt], a[mt], b0, b1);
            }
        }
    }

    #pragma unroll
    for (int nt = 0; nt < 4; nt++) {
        int col = n0 + wn * 32 + nt * 8 + 2 * t;
        float b0 = bias[col], b1 = bias[col + 1];
        #pragma unroll
        for (int mt = 0; mt < 4; mt++) {
            long r = m0 + wm * 64 + mt * 16 + g;
            *(float2*)&C[r * NC + col] =
                make_float2(acc[mt][nt][0] + b0, acc[mt][nt][1] + b1);
            *(float2*)&C[(r + 8) * NC + col] =
                make_float2(acc[mt][nt][2] + b0, acc[mt][nt][3] + b1);
        }
    }
}

// GEMM3 (proj): plain gemm
template<int NC>
__global__ __launch_bounds__(256, 2) void gemm_tc3_kernel(
    const float* __restrict__ A, const float* __restrict__ W,
    const float* __restrict__ bias, float* __restrict__ C)
{
    extern __shared__ float sm[];
    gemm_tc3_body<NC>(A, W, bias, C, sm, (long)blockIdx.y * 128, blockIdx.x * 128);
}

// GEMM1 + fused precomp: extra grid rows (blockIdx.y >= M_TILES) build
// g_comb[h][wm][i][j(pad56)] = (bias + mask) * sqrt(hd); pad cols -1e30.
__global__ __launch_bounds__(256, 2) void gemm1_precomp_kernel(
    const float* __restrict__ A, const float* __restrict__ W,
    const float* __restrict__ bias, float* __restrict__ C,
    const float* __restrict__ mask, const float* __restrict__ bias_table,
    const int* __restrict__ rel_index)
{
    extern __shared__ float sm[];
    if (blockIdx.y >= M_TILES) {
        const int pid = (blockIdx.y - M_TILES) * 3 + blockIdx.x;
        if (pid >= 256) return;
        const int wm = pid & 63, h = pid >> 6;
        const float inv_scale = 5.656854249492381f;  // sqrt(32)
        float* dst = g_comb + ((size_t)h * 64 + wm) * 49 * 56;
        for (int q = threadIdx.x; q < 49 * 56; q += 256) {
            int i = q / 56, j = q - i * 56;
            dst[q] = (j < 49)
                ? (bias_table[rel_index[i * 49 + j] * HEADS + h]
                   + mask[(size_t)wm * (NWIN * NWIN) + i * 49 + j]) * inv_scale
                : -1e30f;
        }
        return;
    }
    gemm_tc3_body<384>(A, W, bias, C, sm, (long)blockIdx.y * 128, blockIdx.x * 128);
}

// ---------------------------------------------------------------------------
// Attention v4 (frozen round-10 winner). Block = (window b, head h), 128 thr.
// ---------------------------------------------------------------------------
__global__ __launch_bounds__(128) void attn_tc_kernel(
    const float* __restrict__ qkv, float* __restrict__ outp)
{
    __shared__ float Qs[64][40];   // rows 49..63 uninit (outputs masked)
    __shared__ float Ks[56][40];   // rows 49..55 zeroed
    __shared__ float Vs[56][40];   // rows 49..55 zeroed
    __shared__ float Ps[64][72];

    const int tid  = threadIdx.x;
    const int lane = tid & 31;
    const int warp = tid >> 5;
    const int g = lane >> 2, t = lane & 3;
    const int b = blockIdx.x >> 2, h = blockIdx.x & 3;
    const float scale = 0.17677669529663687f;   // 32^-0.5

    // ---- cp.async staging of Q, K, V (49 rows x 32 floats each) ----
    {
        const float* base = qkv + ((size_t)b * 49) * 384 + h * 32;
        const uint32_t sQ = (uint32_t)__cvta_generic_to_shared(&Qs[0][0]);
        const uint32_t sK = (uint32_t)__cvta_generic_to_shared(&Ks[0][0]);
        const uint32_t sV = (uint32_t)__cvta_generic_to_shared(&Vs[0][0]);
        for (int q = tid; q < 392; q += 128) {
            int i = q >> 3, seg = q & 7;
            CP_ASYNC16(sQ + (i * 40 + seg * 4) * 4, base + (size_t)i * 384 + seg * 4);
        }
        for (int q = tid; q < 392; q += 128) {
            int i = q >> 3, seg = q & 7;
            CP_ASYNC16(sK + (i * 40 + seg * 4) * 4, base + (size_t)i * 384 + 128 + seg * 4);
        }
        for (int q = tid; q < 392; q += 128) {
            int i = q >> 3, seg = q & 7;
            CP_ASYNC16(sV + (i * 40 + seg * 4) * 4, base + (size_t)i * 384 + 256 + seg * 4);
        }
        CP_COMMIT();
        for (int q = tid; q < 7 * 40; q += 128) {
            int i = 49 + q / 40, c2 = q % 40;
            Ks[i][c2] = 0.f;
            Vs[i][c2] = 0.f;
        }
    }

    // ---- init S accumulators from comb*sqrt(hd) (overlaps with cp.async) ----
    const int r0 = warp * 16 + g;
    const float* comb = g_comb + ((size_t)h * 64 + (b & 63)) * 49 * 56;
    float c[7][4];
    #pragma unroll
    for (int nt = 0; nt < 7; nt++) {
        const int col = nt * 8 + 2 * t;
        if (r0 < 49) {
            float2 f = *(const float2*)&comb[r0 * 56 + col];
            c[nt][0] = f.x; c[nt][1] = f.y;
        } else { c[nt][0] = 0.f; c[nt][1] = 0.f; }
        if (r0 + 8 < 49) {
            float2 f = *(const float2*)&comb[(r0 + 8) * 56 + col];
            c[nt][2] = f.x; c[nt][3] = f.y;
        } else { c[nt][2] = 0.f; c[nt][3] = 0.f; }
    }

    asm volatile("cp.async.wait_group 0;");
    __syncthreads();

    // ---- S' = QK^T + comb*sqrt(hd) ----
    #pragma unroll
    for (int s = 0; s < 4; s++) {
        const int off = s * 8;
        uint32_t a[4];
        a[0] = rna_bits(Qs[r0][off + t]);
        a[1] = rna_bits(Qs[r0 + 8][off + t]);
        a[2] = rna_bits(Qs[r0][off + t + 4]);
        a[3] = rna_bits(Qs[r0 + 8][off + t + 4]);
        #pragma unroll
        for (int nt = 0; nt < 7; nt++) {
            uint32_t b0 = rna_bits(Ks[nt * 8 + g][off + t]);
            uint32_t b1 = rna_bits(Ks[nt * 8 + g][off + t + 4]);
            mma_tf32(c[nt], a, b0, b1);
        }
    }

    // ---- softmax(scale * S') in registers ----
    {
        float mx0 = -1e30f, mx1 = -1e30f;
        #pragma unroll
        for (int nt = 0; nt < 7; nt++) {
            mx0 = fmaxf(mx0, fmaxf(c[nt][0], c[nt][1]));
            mx1 = fmaxf(mx1, fmaxf(c[nt][2], c[nt][3]));
        }
        mx0 = fmaxf(mx0, __shfl_xor_sync(0xffffffffu, mx0, 1));
        mx0 = fmaxf(mx0, __shfl_xor_sync(0xffffffffu, mx0, 2));
        mx1 = fmaxf(mx1, __shfl_xor_sync(0xffffffffu, mx1, 1));
        mx1 = fmaxf(mx1, __shfl_xor_sync(0xffffffffu, mx1, 2));
        float s0 = 0.f, s1 = 0.f;
        #pragma unroll
        for (int nt = 0; nt < 7; nt++) {
            c[nt][0] = __expf((c[nt][0] - mx0) * scale);
            c[nt][1] = __expf((c[nt][1] - mx0) * scale);
            c[nt][2] = __expf((c[nt][2] - mx1) * scale);
            c[nt][3] = __expf((c[nt][3] - mx1) * scale);
            s0 += c[nt][0] + c[nt][1];
            s1 += c[nt][2] + c[nt][3];
        }
        s0 += __shfl_xor_sync(0xffffffffu, s0, 1);
        s0 += __shfl_xor_sync(0xffffffffu, s0, 2);
        s1 += __shfl_xor_sync(0xffffffffu, s1, 1);
        s1 += __shfl_xor_sync(0xffffffffu, s1, 2);
        const float i0 = 1.f / s0, i1 = 1.f / s1;

        #pragma unroll
        for (int nt = 0; nt < 7; nt++) {
            const int col = nt * 8 + 2 * t;
            *(float2*)&Ps[r0][col] =
                make_float2(to_tf32(c[nt][0] * i0), to_tf32(c[nt][1] * i0));
            *(float2*)&Ps[r0 + 8][col] =
                make_float2(to_tf32(c[nt][2] * i1), to_tf32(c[nt][3] * i1));
        }
    }
    __syncwarp();

    // ---- O = P V ----
    float o[4][4];
    #pragma unroll
    for (int nt = 0; nt < 4; nt++)
        #pragma unroll
        for (int e = 0; e < 4; e++) o[nt][e] = 0.f;

    #pragma unroll
    for (int s = 0; s < 7; s++) {
        const int off = s * 8;
        uint32_t a[4];
        a[0] = __float_as_uint(Ps[r0][off + t]);
        a[1] = __float_as_uint(Ps[r0 + 8][off + t]);
        a[2] = __float_as_uint(Ps[r0][off + t + 4]);
        a[3] = __float_as_uint(Ps[r0 + 8][off + t + 4]);
        #pragma unroll
        for (int nt = 0; nt < 4; nt++) {
            uint32_t b0 = rna_bits(Vs[off + t][nt * 8 + g]);
            uint32_t b1 = rna_bits(Vs[off + t + 4][nt * 8 + g]);
            mma_tf32(o[nt], a, b0, b1);
        }
    }

    #pragma unroll
    for (int nt = 0; nt < 4; nt++) {
        const int d = nt * 8 + 2 * t;
        if (r0 < 49)
            *(float2*)&outp[((size_t)b * 49 + r0) * DIMC + h * HD + d]
                = make_float2(o[nt][0], o[nt][1]);
        if (r0 + 8 < 49)
            *(float2*)&outp[((size_t)b * 49 + r0 + 8) * DIMC + h * HD + d]
                = make_float2(o[nt][2], o[nt][3]);
    }
}

// ---------------------------------------------------------------------------
extern "C" void kernel_launch(void* const* d_in, const int* in_sizes, int n_in,
                              void* d_out, int out_size)
{
    const float* x          = (const float*)d_in[0];
    const float* mask       = (const float*)d_in[1];
    const float* qkv_w      = (const float*)d_in[2];
    const float* qkv_b      = (const float*)d_in[3];
    const float* proj_w     = (const float*)d_in[4];
    const float* proj_b     = (const float*)d_in[5];
    const float* bias_table = (const float*)d_in[6];
    const int*   rel_index  = (const int*)d_in[7];
    float*       out        = (float*)d_out;

    float *qkvbuf = nullptr, *attbuf = nullptr;
    cudaGetSymbolAddress((void**)&qkvbuf, g_qkv);
    cudaGetSymbolAddress((void**)&attbuf, g_att);

    cudaFuncSetAttribute(gemm1_precomp_kernel,
                         cudaFuncAttributeMaxDynamicSharedMemorySize, GEMM_SMEM_BYTES);
    cudaFuncSetAttribute(gemm_tc3_kernel<DIMC>,
                         cudaFuncAttributeMaxDynamicSharedMemorySize, GEMM_SMEM_BYTES);

    // GEMM1 with precomp folded in as extra grid rows (86 rows x 3 = 258 blocks)
    dim3 g1(384 / 128, M_TILES + 86);
    gemm1_precomp_kernel<<<g1, 256, GEMM_SMEM_BYTES>>>(
        x, qkv_w, qkv_b, qkvbuf, mask, bias_table, rel_index);

    attn_tc_kernel<<<NB * HEADS, 128>>>(qkvbuf, attbuf);

    dim3 g3(DIMC / 128, M_TILES);
    gemm_tc3_kernel<DIMC><<<g3, 256, GEMM_SMEM_BYTES>>>(attbuf, proj_w, proj_b, out);
}

// round 13
// speedup vs baseline: 1.4017x; 1.1032x over previous
#include <cuda_runtime.h>
#include <cuda_fp16.h>
#include <math.h>
#include <stdint.h>

// Problem constants
#define DIMC   128
#define NWIN   49
#define HEADS  4
#define HD     32
#define NB     4096
#define M_TOTAL (NB * NWIN)        // 200704 = 1568 * 128
#define M_TILES (M_TOTAL / 128)    // 1568

// Scratch (allocation-free rule: static device globals)
__device__ __half g_qkv_h[(size_t)NB * NWIN * 384]; // [M, 384] fp16 q|k|v
__device__ float  g_att[(size_t)NB * NWIN * DIMC];  // [M, 128] attention out
__device__ float  g_comb[4 * 64 * 49 * 56];         // (bias+mask)*sqrt(hd)

__device__ __forceinline__ uint32_t rna_bits(float x) {
    return __float_as_uint(x) + 0x1000u;   // tf32 round-to-nearest as raw bits
}

__device__ __forceinline__ void mma_tf32(float c[4], const uint32_t a[4],
                                         uint32_t b0, uint32_t b1) {
    asm volatile(
        "mma.sync.aligned.m16n8k8.row.col.f32.tf32.tf32.f32 "
        "{%0,%1,%2,%3}, {%4,%5,%6,%7}, {%8,%9}, {%0,%1,%2,%3};"
        : "+f"(c[0]), "+f"(c[1]), "+f"(c[2]), "+f"(c[3])
        : "r"(a[0]), "r"(a[1]), "r"(a[2]), "r"(a[3]), "r"(b0), "r"(b1));
}

__device__ __forceinline__ void mma_f16(float c[4], const uint32_t a[4],
                                        uint32_t b0, uint32_t b1) {
    asm volatile(
        "mma.sync.aligned.m16n8k16.row.col.f32.f16.f16.f32 "
        "{%0,%1,%2,%3}, {%4,%5,%6,%7}, {%8,%9}, {%0,%1,%2,%3};"
        : "+f"(c[0]), "+f"(c[1]), "+f"(c[2]), "+f"(c[3])
        : "r"(a[0]), "r"(a[1]), "r"(a[2]), "r"(a[3]), "r"(b0), "r"(b1));
}

#define CP_ASYNC16(dst, src) \
    asm volatile("cp.async.ca.shared.global [%0], [%1], 16;" :: "r"(dst), "l"(src))
#define CP_COMMIT() asm volatile("cp.async.commit_group;")

// ---------------------------------------------------------------------------
// tf32 GEMM v3 body (frozen winner: 128x128 tile, 8 warps, warp tile 64x32,
// K chunks of 16, 3-stage cp.async ring, stride-20 smem).
// OUT_HALF: epilogue stores __half2 (for the qkv intermediate).
// ---------------------------------------------------------------------------
#define GEMM_SMEM_BYTES (6 * 128 * 20 * 4)

template<int NC, bool OUT_HALF>
__device__ __forceinline__ void gemm_tc3_body(
    const float* __restrict__ A, const float* __restrict__ W,
    const float* __restrict__ bias, void* __restrict__ C,
    float* sm, long m0, int n0)
{
    const int tid  = threadIdx.x;
    const int lane = tid & 31;
    const int warp = tid >> 5;
    const int wm   = warp & 1;
    const int wn   = warp >> 1;
    const int g    = lane >> 2;
    const int t    = lane & 3;

    const int srow = tid >> 2;
    const int sf   = tid & 3;
    const float* gA = A + (m0 + srow) * 128 + sf * 4;
    const float* gW = W + ((size_t)n0 + srow) * 128 + sf * 4;
    const uint32_t sbase = (uint32_t)__cvta_generic_to_shared(sm);
    const uint32_t sA = sbase + (srow * 20 + sf * 4) * 4;
    const uint32_t sW = sA + 3 * 10240;
    const uint32_t BUFB  = 10240;
    const uint32_t ROW64 = 64 * 20 * 4;

    auto stage = [&](int kc, int buf) {
        const float* a = gA + kc * 16;
        const float* w = gW + kc * 16;
        CP_ASYNC16(sA + buf * BUFB,         a);
        CP_ASYNC16(sA + buf * BUFB + ROW64, a + 64 * 128);
        CP_ASYNC16(sW + buf * BUFB,         w);
        CP_ASYNC16(sW + buf * BUFB + ROW64, w + 64 * 128);
    };

    float acc[4][4][4] = {};

    stage(0, 0); CP_COMMIT();
    stage(1, 1); CP_COMMIT();

    #pragma unroll
    for (int kc = 0; kc < 8; kc++) {
        if (kc < 7) asm volatile("cp.async.wait_group 1;");
        else        asm volatile("cp.async.wait_group 0;");
        __syncthreads();
        if (kc < 6) { stage(kc + 2, (kc + 2) % 3); CP_COMMIT(); }

        const float* Ab = sm + (kc % 3) * 2560;
        const float* Wb = Ab + 3 * 2560;

        #pragma unroll
        for (int s = 0; s < 2; s++) {
            const int off = s * 8;
            uint32_t a[4][4];
            #pragma unroll
            for (int mt = 0; mt < 4; mt++) {
                int r = wm * 64 + mt * 16 + g;
                a[mt][0] = rna_bits(Ab[r * 20 + off + t]);
                a[mt][1] = rna_bits(Ab[(r + 8) * 20 + off + t]);
                a[mt][2] = rna_bits(Ab[r * 20 + off + t + 4]);
                a[mt][3] = rna_bits(Ab[(r + 8) * 20 + off + t + 4]);
            }
            #pragma unroll
            for (int nt = 0; nt < 4; nt++) {
                int n = wn * 32 + nt * 8 + g;
                uint32_t b0 = rna_bits(Wb[n * 20 + off + t]);
                uint32_t b1 = rna_bits(Wb[n * 20 + off + t + 4]);
                #pragma unroll
                for (int mt = 0; mt < 4; mt++)
                    mma_tf32(acc[mt][nt], a[mt], b0, b1);
            }
        }
    }

    #pragma unroll
    for (int nt = 0; nt < 4; nt++) {
        int col = n0 + wn * 32 + nt * 8 + 2 * t;
        float b0 = bias[col], b1 = bias[col + 1];
        #pragma unroll
        for (int mt = 0; mt < 4; mt++) {
            long r = m0 + wm * 64 + mt * 16 + g;
            if (OUT_HALF) {
                __half* Ch = (__half*)C;
                *(__half2*)&Ch[r * NC + col] =
                    __floats2half2_rn(acc[mt][nt][0] + b0, acc[mt][nt][1] + b1);
                *(__half2*)&Ch[(r + 8) * NC + col] =
                    __floats2half2_rn(acc[mt][nt][2] + b0, acc[mt][nt][3] + b1);
            } else {
                float* Cf = (float*)C;
                *(float2*)&Cf[r * NC + col] =
                    make_float2(acc[mt][nt][0] + b0, acc[mt][nt][1] + b1);
                *(float2*)&Cf[(r + 8) * NC + col] =
                    make_float2(acc[mt][nt][2] + b0, acc[mt][nt][3] + b1);
            }
        }
    }
}

// GEMM3 (proj): fp32 in, fp32 out
template<int NC>
__global__ __launch_bounds__(256, 2) void gemm_tc3_kernel(
    const float* __restrict__ A, const float* __restrict__ W,
    const float* __restrict__ bias, float* __restrict__ C)
{
    extern __shared__ float sm[];
    gemm_tc3_body<NC, false>(A, W, bias, C, sm, (long)blockIdx.y * 128,
                             blockIdx.x * 128);
}

// GEMM1 (qkv): fp16 out + fused precomp in extra grid rows
__global__ __launch_bounds__(256, 2) void gemm1_precomp_kernel(
    const float* __restrict__ A, const float* __restrict__ W,
    const float* __restrict__ bias, __half* __restrict__ C,
    const float* __restrict__ mask, const float* __restrict__ bias_table,
    const int* __restrict__ rel_index)
{
    extern __shared__ float sm[];
    if (blockIdx.y >= M_TILES) {
        const int pid = (blockIdx.y - M_TILES) * 3 + blockIdx.x;
        if (pid >= 256) return;
        const int wm = pid & 63, h = pid >> 6;
        const float inv_scale = 5.656854249492381f;  // sqrt(32)
        float* dst = g_comb + ((size_t)h * 64 + wm) * 49 * 56;
        for (int q = threadIdx.x; q < 49 * 56; q += 256) {
            int i = q / 56, j = q - i * 56;
            dst[q] = (j < 49)
                ? (bias_table[rel_index[i * 49 + j] * HEADS + h]
                   + mask[(size_t)wm * (NWIN * NWIN) + i * 49 + j]) * inv_scale
                : -1e30f;
        }
        return;
    }
    gemm_tc3_body<384, true>(A, W, bias, C, sm, (long)blockIdx.y * 128,
                             blockIdx.x * 128);
}

// ---------------------------------------------------------------------------
// Attention v5 — fp16 tensor cores (m16n8k16). Block = (window b, head h),
// 128 thr = 4 warps, warp owns 16 rows (r0, r0+8).
// Q/K/V staged fp16 row-major via cp.async, stride 40 halfs (conflict-free).
// QK: 2 k-steps; comb*sqrt(hd) fp32 init; softmax fp32 in registers;
// P -> fp16 smem stride 72 halfs (cols 56..63 zeroed); PV: 4 k-steps,
// B-fragments via paired LDS.U16 (broadcast pairs, conflict-free).
// ---------------------------------------------------------------------------
__global__ __launch_bounds__(128) void attn_tc_kernel(
    const __half* __restrict__ qkv, float* __restrict__ outp)
{
    __shared__ __half Qs[64][40];   // rows 49..63 uninit (outputs masked)
    __shared__ __half Ks[56][40];   // rows 49..55 zeroed
    __shared__ __half Vs[64][40];   // rows 49..63 zeroed
    __shared__ __half Ps[64][72];   // cols 56..63 zeroed at write

    const int tid  = threadIdx.x;
    const int lane = tid & 31;
    const int warp = tid >> 5;
    const int g = lane >> 2, t = lane & 3;
    const int b = blockIdx.x >> 2, h = blockIdx.x & 3;
    const float scale = 0.17677669529663687f;   // 32^-0.5

    // ---- cp.async staging of Q, K, V (49 rows x 32 halfs = 4 x 16B each) ----
    {
        const __half* base = qkv + ((size_t)b * 49) * 384 + h * 32;
        const uint32_t sQ = (uint32_t)__cvta_generic_to_shared(&Qs[0][0]);
        const uint32_t sK = (uint32_t)__cvta_generic_to_shared(&Ks[0][0]);
        const uint32_t sV = (uint32_t)__cvta_generic_to_shared(&Vs[0][0]);
        for (int q = tid; q < 196; q += 128) {
            int i = q >> 2, seg = q & 3;
            CP_ASYNC16(sQ + i * 80 + seg * 16, base + (size_t)i * 384 + seg * 8);
        }
        for (int q = tid; q < 196; q += 128) {
            int i = q >> 2, seg = q & 3;
            CP_ASYNC16(sK + i * 80 + seg * 16, base + (size_t)i * 384 + 128 + seg * 8);
        }
        for (int q = tid; q < 196; q += 128) {
            int i = q >> 2, seg = q & 3;
            CP_ASYNC16(sV + i * 80 + seg * 16, base + (size_t)i * 384 + 256 + seg * 8);
        }
        CP_COMMIT();
        // zero pad rows (as 32-bit words; disjoint from cp.async targets)
        uint32_t* Kw = (uint32_t*)&Ks[49][0];   // 7 rows * 20 words
        for (int q = tid; q < 140; q += 128) Kw[q] = 0u;
        uint32_t* Vw = (uint32_t*)&Vs[49][0];   // 15 rows * 20 words
        for (int q = tid; q < 300; q += 128) Vw[q] = 0u;
    }

    // ---- init S accumulators from comb*sqrt(hd) (overlaps with cp.async) ----
    const int r0 = warp * 16 + g;
    const float* comb = g_comb + ((size_t)h * 64 + (b & 63)) * 49 * 56;
    float c[7][4];
    #pragma unroll
    for (int nt = 0; nt < 7; nt++) {
        const int col = nt * 8 + 2 * t;
        if (r0 < 49) {
            float2 f = *(const float2*)&comb[r0 * 56 + col];
            c[nt][0] = f.x; c[nt][1] = f.y;
        } else { c[nt][0] = 0.f; c[nt][1] = 0.f; }
        if (r0 + 8 < 49) {
            float2 f = *(const float2*)&comb[(r0 + 8) * 56 + col];
            c[nt][2] = f.x; c[nt][3] = f.y;
        } else { c[nt][2] = 0.f; c[nt][3] = 0.f; }
    }

    asm volatile("cp.async.wait_group 0;");
    __syncthreads();

    // ---- S' = QK^T + comb*sqrt(hd)  (2 x m16n8k16 k-steps) ----
    #pragma unroll
    for (int s = 0; s < 2; s++) {
        const int k0 = s * 16;
        uint32_t a[4];
        a[0] = *(const uint32_t*)&Qs[r0][k0 + 2 * t];
        a[1] = *(const uint32_t*)&Qs[r0 + 8][k0 + 2 * t];
        a[2] = *(const uint32_t*)&Qs[r0][k0 + 8 + 2 * t];
        a[3] = *(const uint32_t*)&Qs[r0 + 8][k0 + 8 + 2 * t];
        #pragma unroll
        for (int nt = 0; nt < 7; nt++) {
            const int n = nt * 8 + g;
            uint32_t b0 = *(const uint32_t*)&Ks[n][k0 + 2 * t];
            uint32_t b1 = *(const uint32_t*)&Ks[n][k0 + 8 + 2 * t];
            mma_f16(c[nt], a, b0, b1);
        }
    }

    // ---- softmax(scale * S') in registers ----
    {
        float mx0 = -1e30f, mx1 = -1e30f;
        #pragma unroll
        for (int nt = 0; nt < 7; nt++) {
            mx0 = fmaxf(mx0, fmaxf(c[nt][0], c[nt][1]));
            mx1 = fmaxf(mx1, fmaxf(c[nt][2], c[nt][3]));
        }
        mx0 = fmaxf(mx0, __shfl_xor_sync(0xffffffffu, mx0, 1));
        mx0 = fmaxf(mx0, __shfl_xor_sync(0xffffffffu, mx0, 2));
        mx1 = fmaxf(mx1, __shfl_xor_sync(0xffffffffu, mx1, 1));
        mx1 = fmaxf(mx1, __shfl_xor_sync(0xffffffffu, mx1, 2));
        float s0 = 0.f, s1 = 0.f;
        #pragma unroll
        for (int nt = 0; nt < 7; nt++) {
            c[nt][0] = __expf((c[nt][0] - mx0) * scale);
            c[nt][1] = __expf((c[nt][1] - mx0) * scale);
            c[nt][2] = __expf((c[nt][2] - mx1) * scale);
            c[nt][3] = __expf((c[nt][3] - mx1) * scale);
            s0 += c[nt][0] + c[nt][1];
            s1 += c[nt][2] + c[nt][3];
        }
        s0 += __shfl_xor_sync(0xffffffffu, s0, 1);
        s0 += __shfl_xor_sync(0xffffffffu, s0, 2);
        s1 += __shfl_xor_sync(0xffffffffu, s1, 1);
        s1 += __shfl_xor_sync(0xffffffffu, s1, 2);
        const float i0 = 1.f / s0, i1 = 1.f / s1;

        #pragma unroll
        for (int nt = 0; nt < 7; nt++) {
            const int col = nt * 8 + 2 * t;
            *(__half2*)&Ps[r0][col] =
                __floats2half2_rn(c[nt][0] * i0, c[nt][1] * i0);
            *(__half2*)&Ps[r0 + 8][col] =
                __floats2half2_rn(c[nt][2] * i1, c[nt][3] * i1);
        }
        // zero pad cols 56..63 (PV k-range is 0..63)
        *(__half2*)&Ps[r0][56 + 2 * t]     = __floats2half2_rn(0.f, 0.f);
        *(__half2*)&Ps[r0 + 8][56 + 2 * t] = __floats2half2_rn(0.f, 0.f);
    }
    __syncwarp();

    // ---- O = P V  (4 x m16n8k16 k-steps) ----
    float o[4][4];
    #pragma unroll
    for (int nt = 0; nt < 4; nt++)
        #pragma unroll
        for (int e = 0; e < 4; e++) o[nt][e] = 0.f;

    #pragma unroll
    for (int s = 0; s < 4; s++) {
        const int k0 = s * 16;
        uint32_t a[4];
        a[0] = *(const uint32_t*)&Ps[r0][k0 + 2 * t];
        a[1] = *(const uint32_t*)&Ps[r0 + 8][k0 + 2 * t];
        a[2] = *(const uint32_t*)&Ps[r0][k0 + 8 + 2 * t];
        a[3] = *(const uint32_t*)&Ps[r0 + 8][k0 + 8 + 2 * t];
        #pragma unroll
        for (int nt = 0; nt < 4; nt++) {
            const int n = nt * 8 + g;
            uint32_t b0 = (uint32_t)*(const unsigned short*)&Vs[k0 + 2 * t][n]
                        | ((uint32_t)*(const unsigned short*)&Vs[k0 + 2 * t + 1][n] << 16);
            uint32_t b1 = (uint32_t)*(const unsigned short*)&Vs[k0 + 8 + 2 * t][n]
                        | ((uint32_t)*(const unsigned short*)&Vs[k0 + 9 + 2 * t][n] << 16);
            mma_f16(o[nt], a, b0, b1);
        }
    }

    #pragma unroll
    for (int nt = 0; nt < 4; nt++) {
        const int d = nt * 8 + 2 * t;
        if (r0 < 49)
            *(float2*)&outp[((size_t)b * 49 + r0) * DIMC + h * HD + d]
                = make_float2(o[nt][0], o[nt][1]);
        if (r0 + 8 < 49)
            *(float2*)&outp[((size_t)b * 49 + r0 + 8) * DIMC + h * HD + d]
                = make_float2(o[nt][2], o[nt][3]);
    }
}

// ---------------------------------------------------------------------------
extern "C" void kernel_launch(void* const* d_in, const int* in_sizes, int n_in,
                              void* d_out, int out_size)
{
    const float* x          = (const float*)d_in[0];
    const float* mask       = (const float*)d_in[1];
    const float* qkv_w      = (const float*)d_in[2];
    const float* qkv_b      = (const float*)d_in[3];
    const float* proj_w     = (const float*)d_in[4];
    const float* proj_b     = (const float*)d_in[5];
    const float* bias_table = (const float*)d_in[6];
    const int*   rel_index  = (const int*)d_in[7];
    float*       out        = (float*)d_out;

    __half* qkvbuf = nullptr;
    float*  attbuf = nullptr;
    cudaGetSymbolAddress((void**)&qkvbuf, g_qkv_h);
    cudaGetSymbolAddress((void**)&attbuf, g_att);

    cudaFuncSetAttribute(gemm1_precomp_kernel,
                         cudaFuncAttributeMaxDynamicSharedMemorySize, GEMM_SMEM_BYTES);
    cudaFuncSetAttribute(gemm_tc3_kernel<DIMC>,
                         cudaFuncAttributeMaxDynamicSharedMemorySize, GEMM_SMEM_BYTES);

    // GEMM1 (fp16 out) with precomp folded in as extra grid rows
    dim3 g1(384 / 128, M_TILES + 86);
    gemm1_precomp_kernel<<<g1, 256, GEMM_SMEM_BYTES>>>(
        x, qkv_w, qkv_b, qkvbuf, mask, bias_table, rel_index);

    attn_tc_kernel<<<NB * HEADS, 128>>>(qkvbuf, attbuf);

    dim3 g3(DIMC / 128, M_TILES);
    gemm_tc3_kernel<DIMC><<<g3, 256, GEMM_SMEM_BYTES>>>(attbuf, proj_w, proj_b, out);
}

// round 14
// speedup vs baseline: 1.4674x; 1.0469x over previous
#include <cuda_runtime.h>
#include <cuda_fp16.h>
#include <math.h>
#include <stdint.h>

// Problem constants
#define DIMC   128
#define NWIN   49
#define HEADS  4
#define HD     32
#define NB     4096
#define M_TOTAL (NB * NWIN)        // 200704 = 1568 * 128
#define M_TILES (M_TOTAL / 128)    // 1568

// Scratch (allocation-free rule: static device globals)
__device__ __half g_qkv_h[(size_t)NB * NWIN * 384]; // [M, 384] fp16 q|k|v
__device__ __half g_att_h[(size_t)NB * NWIN * DIMC];// [M, 128] fp16 attn out
__device__ __half g_projw_h[DIMC * DIMC];           // fp16 proj_w
__device__ float  g_comb[4 * 64 * 49 * 56];         // (bias+mask)*sqrt(hd)

__device__ __forceinline__ uint32_t rna_bits(float x) {
    return __float_as_uint(x) + 0x1000u;   // tf32 round-to-nearest as raw bits
}

__device__ __forceinline__ void mma_tf32(float c[4], const uint32_t a[4],
                                         uint32_t b0, uint32_t b1) {
    asm volatile(
        "mma.sync.aligned.m16n8k8.row.col.f32.tf32.tf32.f32 "
        "{%0,%1,%2,%3}, {%4,%5,%6,%7}, {%8,%9}, {%0,%1,%2,%3};"
        : "+f"(c[0]), "+f"(c[1]), "+f"(c[2]), "+f"(c[3])
        : "r"(a[0]), "r"(a[1]), "r"(a[2]), "r"(a[3]), "r"(b0), "r"(b1));
}

__device__ __forceinline__ void mma_f16(float c[4], const uint32_t a[4],
                                        uint32_t b0, uint32_t b1) {
    asm volatile(
        "mma.sync.aligned.m16n8k16.row.col.f32.f16.f16.f32 "
        "{%0,%1,%2,%3}, {%4,%5,%6,%7}, {%8,%9}, {%0,%1,%2,%3};"
        : "+f"(c[0]), "+f"(c[1]), "+f"(c[2]), "+f"(c[3])
        : "r"(a[0]), "r"(a[1]), "r"(a[2]), "r"(a[3]), "r"(b0), "r"(b1));
}

#define CP_ASYNC16(dst, src) \
    asm volatile("cp.async.ca.shared.global [%0], [%1], 16;" :: "r"(dst), "l"(src))
#define CP_COMMIT() asm volatile("cp.async.commit_group;")

// ---------------------------------------------------------------------------
// tf32 GEMM v3 body (frozen winner) — fp16 output epilogue for GEMM1.
// ---------------------------------------------------------------------------
#define GEMM_SMEM_BYTES (6 * 128 * 20 * 4)

__device__ __forceinline__ void gemm_tc3_body_h(
    const float* __restrict__ A, const float* __restrict__ W,
    const float* __restrict__ bias, __half* __restrict__ C,
    float* sm, long m0, int n0)
{
    const int tid  = threadIdx.x;
    const int lane = tid & 31;
    const int warp = tid >> 5;
    const int wm   = warp & 1;
    const int wn   = warp >> 1;
    const int g    = lane >> 2;
    const int t    = lane & 3;

    const int srow = tid >> 2;
    const int sf   = tid & 3;
    const float* gA = A + (m0 + srow) * 128 + sf * 4;
    const float* gW = W + ((size_t)n0 + srow) * 128 + sf * 4;
    const uint32_t sbase = (uint32_t)__cvta_generic_to_shared(sm);
    const uint32_t sA = sbase + (srow * 20 + sf * 4) * 4;
    const uint32_t sW = sA + 3 * 10240;
    const uint32_t BUFB  = 10240;
    const uint32_t ROW64 = 64 * 20 * 4;

    auto stage = [&](int kc, int buf) {
        const float* a = gA + kc * 16;
        const float* w = gW + kc * 16;
        CP_ASYNC16(sA + buf * BUFB,         a);
        CP_ASYNC16(sA + buf * BUFB + ROW64, a + 64 * 128);
        CP_ASYNC16(sW + buf * BUFB,         w);
        CP_ASYNC16(sW + buf * BUFB + ROW64, w + 64 * 128);
    };

    float acc[4][4][4] = {};

    stage(0, 0); CP_COMMIT();
    stage(1, 1); CP_COMMIT();

    #pragma unroll
    for (int kc = 0; kc < 8; kc++) {
        if (kc < 7) asm volatile("cp.async.wait_group 1;");
        else        asm volatile("cp.async.wait_group 0;");
        __syncthreads();
        if (kc < 6) { stage(kc + 2, (kc + 2) % 3); CP_COMMIT(); }

        const float* Ab = sm + (kc % 3) * 2560;
        const float* Wb = Ab + 3 * 2560;

        #pragma unroll
        for (int s = 0; s < 2; s++) {
            const int off = s * 8;
            uint32_t a[4][4];
            #pragma unroll
            for (int mt = 0; mt < 4; mt++) {
                int r = wm * 64 + mt * 16 + g;
                a[mt][0] = rna_bits(Ab[r * 20 + off + t]);
                a[mt][1] = rna_bits(Ab[(r + 8) * 20 + off + t]);
                a[mt][2] = rna_bits(Ab[r * 20 + off + t + 4]);
                a[mt][3] = rna_bits(Ab[(r + 8) * 20 + off + t + 4]);
            }
            #pragma unroll
            for (int nt = 0; nt < 4; nt++) {
                int n = wn * 32 + nt * 8 + g;
                uint32_t b0 = rna_bits(Wb[n * 20 + off + t]);
                uint32_t b1 = rna_bits(Wb[n * 20 + off + t + 4]);
                #pragma unroll
                for (int mt = 0; mt < 4; mt++)
                    mma_tf32(acc[mt][nt], a[mt], b0, b1);
            }
        }
    }

    #pragma unroll
    for (int nt = 0; nt < 4; nt++) {
        int col = n0 + wn * 32 + nt * 8 + 2 * t;
        float b0 = bias[col], b1 = bias[col + 1];
        #pragma unroll
        for (int mt = 0; mt < 4; mt++) {
            long r = m0 + wm * 64 + mt * 16 + g;
            *(__half2*)&C[r * 384 + col] =
                __floats2half2_rn(acc[mt][nt][0] + b0, acc[mt][nt][1] + b1);
            *(__half2*)&C[(r + 8) * 384 + col] =
                __floats2half2_rn(acc[mt][nt][2] + b0, acc[mt][nt][3] + b1);
        }
    }
}

// GEMM1 (qkv, fp16 out) + fused precomp + proj_w fp16 conversion
__global__ __launch_bounds__(256, 2) void gemm1_precomp_kernel(
    const float* __restrict__ A, const float* __restrict__ W,
    const float* __restrict__ bias, __half* __restrict__ C,
    const float* __restrict__ mask, const float* __restrict__ bias_table,
    const int* __restrict__ rel_index, const float* __restrict__ proj_w)
{
    extern __shared__ float sm[];
    if (blockIdx.y >= M_TILES) {
        const int pid = (blockIdx.y - M_TILES) * 3 + blockIdx.x;
        if (pid < 256) {
            const int wm = pid & 63, h = pid >> 6;
            const float inv_scale = 5.656854249492381f;  // sqrt(32)
            float* dst = g_comb + ((size_t)h * 64 + wm) * 49 * 56;
            for (int q = threadIdx.x; q < 49 * 56; q += 256) {
                int i = q / 56, j = q - i * 56;
                dst[q] = (j < 49)
                    ? (bias_table[rel_index[i * 49 + j] * HEADS + h]
                       + mask[(size_t)wm * (NWIN * NWIN) + i * 49 + j]) * inv_scale
                    : -1e30f;
            }
        } else if (pid < 258) {
            // convert proj_w to fp16 (2 blocks x 256 thr x 32 elems)
            const int base = (pid - 256) * 8192;
            for (int q = threadIdx.x; q < 8192; q += 256)
                g_projw_h[base + q] = __float2half(proj_w[base + q]);
        }
        return;
    }
    gemm_tc3_body_h(A, W, bias, C, sm, (long)blockIdx.y * 128, blockIdx.x * 128);
}

// ---------------------------------------------------------------------------
// GEMM3 fp16 (m16n8k16): out[M,128] = Ah[M,128] * Wh[128,128]^T + bias
// Same macro-structure as the frozen winner (128x128 tile, 8 warps, warp
// tile 64x32, 8 K-chunks of 16 halfs, 3-stage cp.async ring), but fp16
// operands: 1 mma k-step per chunk (16 mma + 24 LDS per chunk per warp,
// half of the tf32 version). Row stride 24 halfs (12 words): fragment
// LDS.32 conflict-free (12g+t mod 32 distinct).
// ---------------------------------------------------------------------------
#define H16_BUFB 6144                            // 128*24*2 bytes per array buf
#define GEMM_H16_SMEM (6 * H16_BUFB)             // 36864

__global__ __launch_bounds__(256, 2) void gemm_h16_kernel(
    const __half* __restrict__ A, const __half* __restrict__ W,
    const float* __restrict__ bias, float* __restrict__ C)
{
    extern __shared__ float smf[];
    __half* sm = (__half*)smf;

    const int tid  = threadIdx.x;
    const int lane = tid & 31;
    const int warp = tid >> 5;
    const int wm   = warp & 1;
    const int wn   = warp >> 1;
    const int g    = lane >> 2;
    const int t    = lane & 3;
    const long m0  = (long)blockIdx.y * 128;

    // staging: chunk = 16 halfs (32B) per row; thread moves 1 A line + 1 W line
    const int srow = tid >> 1;                   // 0..127
    const int sf   = (tid & 1) * 8;              // half-offset 0 or 8
    const __half* gA = A + (m0 + srow) * 128 + sf;
    const __half* gW = W + srow * 128 + sf;
    const uint32_t sbase = (uint32_t)__cvta_generic_to_shared(sm);
    const uint32_t sA = sbase + (srow * 24 + sf) * 2;
    const uint32_t sW = sA + 3 * H16_BUFB;

    auto stage = [&](int kc, int buf) {
        CP_ASYNC16(sA + buf * H16_BUFB, gA + kc * 16);
        CP_ASYNC16(sW + buf * H16_BUFB, gW + kc * 16);
    };

    float acc[4][4][4] = {};

    stage(0, 0); CP_COMMIT();
    stage(1, 1); CP_COMMIT();

    #pragma unroll
    for (int kc = 0; kc < 8; kc++) {
        if (kc < 7) asm volatile("cp.async.wait_group 1;");
        else        asm volatile("cp.async.wait_group 0;");
        __syncthreads();
        if (kc < 6) { stage(kc + 2, (kc + 2) % 3); CP_COMMIT(); }

        const uint32_t* Aw = (const uint32_t*)(sm + (kc % 3) * 128 * 24);
        const uint32_t* Ww = Aw + 3 * (128 * 24 / 2);

        uint32_t a[4][4];
        #pragma unroll
        for (int mt = 0; mt < 4; mt++) {
            const int r = wm * 64 + mt * 16 + g;
            a[mt][0] = Aw[r * 12 + t];
            a[mt][1] = Aw[(r + 8) * 12 + t];
            a[mt][2] = Aw[r * 12 + 4 + t];
            a[mt][3] = Aw[(r + 8) * 12 + 4 + t];
        }
        #pragma unroll
        for (int nt = 0; nt < 4; nt++) {
            const int n = wn * 32 + nt * 8 + g;
            uint32_t b0 = Ww[n * 12 + t];
            uint32_t b1 = Ww[n * 12 + 4 + t];
            #pragma unroll
            for (int mt = 0; mt < 4; mt++)
                mma_f16(acc[mt][nt], a[mt], b0, b1);
        }
    }

    #pragma unroll
    for (int nt = 0; nt < 4; nt++) {
        const int col = wn * 32 + nt * 8 + 2 * t;
        const float b0 = bias[col], b1 = bias[col + 1];
        #pragma unroll
        for (int mt = 0; mt < 4; mt++) {
            const long r = m0 + wm * 64 + mt * 16 + g;
            *(float2*)&C[r * DIMC + col] =
                make_float2(acc[mt][nt][0] + b0, acc[mt][nt][1] + b1);
            *(float2*)&C[(r + 8) * DIMC + col] =
                make_float2(acc[mt][nt][2] + b0, acc[mt][nt][3] + b1);
        }
    }
}

// ---------------------------------------------------------------------------
// Attention v5 (frozen round-13 winner) — now stores O as fp16.
// ---------------------------------------------------------------------------
__global__ __launch_bounds__(128) void attn_tc_kernel(
    const __half* __restrict__ qkv, __half* __restrict__ outp)
{
    __shared__ __half Qs[64][40];
    __shared__ __half Ks[56][40];
    __shared__ __half Vs[64][40];
    __shared__ __half Ps[64][72];

    const int tid  = threadIdx.x;
    const int lane = tid & 31;
    const int warp = tid >> 5;
    const int g = lane >> 2, t = lane & 3;
    const int b = blockIdx.x >> 2, h = blockIdx.x & 3;
    const float scale = 0.17677669529663687f;   // 32^-0.5

    {
        const __half* base = qkv + ((size_t)b * 49) * 384 + h * 32;
        const uint32_t sQ = (uint32_t)__cvta_generic_to_shared(&Qs[0][0]);
        const uint32_t sK = (uint32_t)__cvta_generic_to_shared(&Ks[0][0]);
        const uint32_t sV = (uint32_t)__cvta_generic_to_shared(&Vs[0][0]);
        for (int q = tid; q < 196; q += 128) {
            int i = q >> 2, seg = q & 3;
            CP_ASYNC16(sQ + i * 80 + seg * 16, base + (size_t)i * 384 + seg * 8);
        }
        for (int q = tid; q < 196; q += 128) {
            int i = q >> 2, seg = q & 3;
            CP_ASYNC16(sK + i * 80 + seg * 16, base + (size_t)i * 384 + 128 + seg * 8);
        }
        for (int q = tid; q < 196; q += 128) {
            int i = q >> 2, seg = q & 3;
            CP_ASYNC16(sV + i * 80 + seg * 16, base + (size_t)i * 384 + 256 + seg * 8);
        }
        CP_COMMIT();
        uint32_t* Kw = (uint32_t*)&Ks[49][0];
        for (int q = tid; q < 140; q += 128) Kw[q] = 0u;
        uint32_t* Vw = (uint32_t*)&Vs[49][0];
        for (int q = tid; q < 300; q += 128) Vw[q] = 0u;
    }

    const int r0 = warp * 16 + g;
    const float* comb = g_comb + ((size_t)h * 64 + (b & 63)) * 49 * 56;
    float c[7][4];
    #pragma unroll
    for (int nt = 0; nt < 7; nt++) {
        const int col = nt * 8 + 2 * t;
        if (r0 < 49) {
            float2 f = *(const float2*)&comb[r0 * 56 + col];
            c[nt][0] = f.x; c[nt][1] = f.y;
        } else { c[nt][0] = 0.f; c[nt][1] = 0.f; }
        if (r0 + 8 < 49) {
            float2 f = *(const float2*)&comb[(r0 + 8) * 56 + col];
            c[nt][2] = f.x; c[nt][3] = f.y;
        } else { c[nt][2] = 0.f; c[nt][3] = 0.f; }
    }

    asm volatile("cp.async.wait_group 0;");
    __syncthreads();

    #pragma unroll
    for (int s = 0; s < 2; s++) {
        const int k0 = s * 16;
        uint32_t a[4];
        a[0] = *(const uint32_t*)&Qs[r0][k0 + 2 * t];
        a[1] = *(const uint32_t*)&Qs[r0 + 8][k0 + 2 * t];
        a[2] = *(const uint32_t*)&Qs[r0][k0 + 8 + 2 * t];
        a[3] = *(const uint32_t*)&Qs[r0 + 8][k0 + 8 + 2 * t];
        #pragma unroll
        for (int nt = 0; nt < 7; nt++) {
            const int n = nt * 8 + g;
            uint32_t b0 = *(const uint32_t*)&Ks[n][k0 + 2 * t];
            uint32_t b1 = *(const uint32_t*)&Ks[n][k0 + 8 + 2 * t];
            mma_f16(c[nt], a, b0, b1);
        }
    }

    {
        float mx0 = -1e30f, mx1 = -1e30f;
        #pragma unroll
        for (int nt = 0; nt < 7; nt++) {
            mx0 = fmaxf(mx0, fmaxf(c[nt][0], c[nt][1]));
            mx1 = fmaxf(mx1, fmaxf(c[nt][2], c[nt][3]));
        }
        mx0 = fmaxf(mx0, __shfl_xor_sync(0xffffffffu, mx0, 1));
        mx0 = fmaxf(mx0, __shfl_xor_sync(0xffffffffu, mx0, 2));
        mx1 = fmaxf(mx1, __shfl_xor_sync(0xffffffffu, mx1, 1));
        mx1 = fmaxf(mx1, __shfl_xor_sync(0xffffffffu, mx1, 2));
        float s0 = 0.f, s1 = 0.f;
        #pragma unroll
        for (int nt = 0; nt < 7; nt++) {
            c[nt][0] = __expf((c[nt][0] - mx0) * scale);
            c[nt][1] = __expf((c[nt][1] - mx0) * scale);
            c[nt][2] = __expf((c[nt][2] - mx1) * scale);
            c[nt][3] = __expf((c[nt][3] - mx1) * scale);
            s0 += c[nt][0] + c[nt][1];
            s1 += c[nt][2] + c[nt][3];
        }
        s0 += __shfl_xor_sync(0xffffffffu, s0, 1);
        s0 += __shfl_xor_sync(0xffffffffu, s0, 2);
        s1 += __shfl_xor_sync(0xffffffffu, s1, 1);
        s1 += __shfl_xor_sync(0xffffffffu, s1, 2);
        const float i0 = 1.f / s0, i1 = 1.f / s1;

        #pragma unroll
        for (int nt = 0; nt < 7; nt++) {
            const int col = nt * 8 + 2 * t;
            *(__half2*)&Ps[r0][col] =
                __floats2half2_rn(c[nt][0] * i0, c[nt][1] * i0);
            *(__half2*)&Ps[r0 + 8][col] =
                __floats2half2_rn(c[nt][2] * i1, c[nt][3] * i1);
        }
        *(__half2*)&Ps[r0][56 + 2 * t]     = __floats2half2_rn(0.f, 0.f);
        *(__half2*)&Ps[r0 + 8][56 + 2 * t] = __floats2half2_rn(0.f, 0.f);
    }
    __syncwarp();

    float o[4][4];
    #pragma unroll
    for (int nt = 0; nt < 4; nt++)
        #pragma unroll
        for (int e = 0; e < 4; e++) o[nt][e] = 0.f;

    #pragma unroll
    for (int s = 0; s < 4; s++) {
        const int k0 = s * 16;
        uint32_t a[4];
        a[0] = *(const uint32_t*)&Ps[r0][k0 + 2 * t];
        a[1] = *(const uint32_t*)&Ps[r0 + 8][k0 + 2 * t];
        a[2] = *(const uint32_t*)&Ps[r0][k0 + 8 + 2 * t];
        a[3] = *(const uint32_t*)&Ps[r0 + 8][k0 + 8 + 2 * t];
        #pragma unroll
        for (int nt = 0; nt < 4; nt++) {
            const int n = nt * 8 + g;
            uint32_t b0 = (uint32_t)*(const unsigned short*)&Vs[k0 + 2 * t][n]
                        | ((uint32_t)*(const unsigned short*)&Vs[k0 + 2 * t + 1][n] << 16);
            uint32_t b1 = (uint32_t)*(const unsigned short*)&Vs[k0 + 8 + 2 * t][n]
                        | ((uint32_t)*(const unsigned short*)&Vs[k0 + 9 + 2 * t][n] << 16);
            mma_f16(o[nt], a, b0, b1);
        }
    }

    #pragma unroll
    for (int nt = 0; nt < 4; nt++) {
        const int d = nt * 8 + 2 * t;
        if (r0 < 49)
            *(__half2*)&outp[((size_t)b * 49 + r0) * DIMC + h * HD + d]
                = __floats2half2_rn(o[nt][0], o[nt][1]);
        if (r0 + 8 < 49)
            *(__half2*)&outp[((size_t)b * 49 + r0 + 8) * DIMC + h * HD + d]
                = __floats2half2_rn(o[nt][2], o[nt][3]);
    }
}

// ---------------------------------------------------------------------------
extern "C" void kernel_launch(void* const* d_in, const int* in_sizes, int n_in,
                              void* d_out, int out_size)
{
    const float* x          = (const float*)d_in[0];
    const float* mask       = (const float*)d_in[1];
    const float* qkv_w      = (const float*)d_in[2];
    const float* qkv_b      = (const float*)d_in[3];
    const float* proj_w     = (const float*)d_in[4];
    const float* proj_b     = (const float*)d_in[5];
    const float* bias_table = (const float*)d_in[6];
    const int*   rel_index  = (const int*)d_in[7];
    float*       out        = (float*)d_out;

    __half *qkvbuf = nullptr, *attbuf = nullptr, *pwbuf = nullptr;
    cudaGetSymbolAddress((void**)&qkvbuf, g_qkv_h);
    cudaGetSymbolAddress((void**)&attbuf, g_att_h);
    cudaGetSymbolAddress((void**)&pwbuf, g_projw_h);

    cudaFuncSetAttribute(gemm1_precomp_kernel,
                         cudaFuncAttributeMaxDynamicSharedMemorySize, GEMM_SMEM_BYTES);
    cudaFuncSetAttribute(gemm_h16_kernel,
                         cudaFuncAttributeMaxDynamicSharedMemorySize, GEMM_H16_SMEM);

    // GEMM1 (fp16 out) + precomp + proj_w conversion as extra grid rows
    dim3 g1(384 / 128, M_TILES + 86);
    gemm1_precomp_kernel<<<g1, 256, GEMM_SMEM_BYTES>>>(
        x, qkv_w, qkv_b, qkvbuf, mask, bias_table, rel_index, proj_w);

    attn_tc_kernel<<<NB * HEADS, 128>>>(qkvbuf, attbuf);

    dim3 g3(1, M_TILES);
    gemm_h16_kernel<<<g3, 256, GEMM_H16_SMEM>>>(attbuf, pwbuf, proj_b, out);
}

// round 15
// speedup vs baseline: 1.5404x; 1.0497x over previous
#include <cuda_runtime.h>
#include <cuda_fp16.h>
#include <math.h>
#include <stdint.h>

// Problem constants
#define DIMC   128
#define NWIN   49
#define HEADS  4
#define HD     32
#define NB     4096
#define M_TOTAL (NB * NWIN)        // 200704 = 1568 * 128
#define M_TILES (M_TOTAL / 128)    // 1568

// Scratch (allocation-free rule: static device globals)
__device__ __half g_qkv_h[(size_t)NB * NWIN * 384]; // [M, 384] fp16 q|k|v
__device__ __half g_att_h[(size_t)NB * NWIN * DIMC];// [M, 128] fp16 attn out
__device__ __half g_projw_h[DIMC * DIMC];           // fp16 proj_w
__device__ float  g_comb[4 * 64 * 49 * 56];         // (bias+mask)*sqrt(hd)

__device__ __forceinline__ void mma_f16(float c[4], const uint32_t a[4],
                                        uint32_t b0, uint32_t b1) {
    asm volatile(
        "mma.sync.aligned.m16n8k16.row.col.f32.f16.f16.f32 "
        "{%0,%1,%2,%3}, {%4,%5,%6,%7}, {%8,%9}, {%0,%1,%2,%3};"
        : "+f"(c[0]), "+f"(c[1]), "+f"(c[2]), "+f"(c[3])
        : "r"(a[0]), "r"(a[1]), "r"(a[2]), "r"(a[3]), "r"(b0), "r"(b1));
}

__device__ __forceinline__ uint32_t packh2(float2 f) {
    __half2 h = __floats2half2_rn(f.x, f.y);   // low = f.x (k even), high = f.y
    return *(uint32_t*)&h;
}

#define CP_ASYNC16(dst, src) \
    asm volatile("cp.async.ca.shared.global [%0], [%1], 16;" :: "r"(dst), "l"(src))
#define CP_COMMIT() asm volatile("cp.async.commit_group;")

// ---------------------------------------------------------------------------
// GEMM1 v7: fp16 tensor cores with convert-at-fragment-load.
// C[M][384] = A[M][128] * W[384][128]^T + bias, fp16 output.
// Frozen macro-structure (128x128 tile, 8 warps, warp tile 64x32, K chunks
// of 16, 3-stage cp.async ring) but fragments are float2 LDS.64 +
// __floats2half2_rn feeding m16n8k16 -> 16 mma/chunk instead of 32,
// ~64 instr/chunk instead of 112. Row stride 24 floats: per-half-warp
// word sets {24g mod 32 + 0..7} disjoint -> conflict-free LDS.64.
// ---------------------------------------------------------------------------
#define G1_ROWF   24
#define G1_BUFB   (128 * G1_ROWF * 4)            // 12288 B per array buf
#define GEMM_SMEM_BYTES (6 * G1_BUFB)            // 73728

__device__ __forceinline__ void gemm_f16cvt_body(
    const float* __restrict__ A, const float* __restrict__ W,
    const float* __restrict__ bias, __half* __restrict__ C,
    float* sm, long m0, int n0)
{
    const int tid  = threadIdx.x;
    const int lane = tid & 31;
    const int warp = tid >> 5;
    const int wm   = warp & 1;
    const int wn   = warp >> 1;
    const int g    = lane >> 2;
    const int t    = lane & 3;

    const int srow = tid >> 2;
    const int sf   = tid & 3;
    const float* gA = A + (m0 + srow) * 128 + sf * 4;
    const float* gW = W + ((size_t)n0 + srow) * 128 + sf * 4;
    const uint32_t sbase = (uint32_t)__cvta_generic_to_shared(sm);
    const uint32_t sA = sbase + (srow * G1_ROWF + sf * 4) * 4;
    const uint32_t sW = sA + 3 * G1_BUFB;
    const uint32_t ROW64 = 64 * G1_ROWF * 4;

    auto stage = [&](int kc, int buf) {
        const float* a = gA + kc * 16;
        const float* w = gW + kc * 16;
        CP_ASYNC16(sA + buf * G1_BUFB,         a);
        CP_ASYNC16(sA + buf * G1_BUFB + ROW64, a + 64 * 128);
        CP_ASYNC16(sW + buf * G1_BUFB,         w);
        CP_ASYNC16(sW + buf * G1_BUFB + ROW64, w + 64 * 128);
    };

    float acc[4][4][4] = {};

    stage(0, 0); CP_COMMIT();
    stage(1, 1); CP_COMMIT();

    #pragma unroll
    for (int kc = 0; kc < 8; kc++) {
        if (kc < 7) asm volatile("cp.async.wait_group 1;");
        else        asm volatile("cp.async.wait_group 0;");
        __syncthreads();
        if (kc < 6) { stage(kc + 2, (kc + 2) % 3); CP_COMMIT(); }

        const float* Ab = sm + (kc % 3) * (128 * G1_ROWF);
        const float* Wb = Ab + 3 * (128 * G1_ROWF);

        uint32_t a[4][4];
        #pragma unroll
        for (int mt = 0; mt < 4; mt++) {
            const int r = wm * 64 + mt * 16 + g;
            a[mt][0] = packh2(*(const float2*)&Ab[r * G1_ROWF + 2 * t]);
            a[mt][1] = packh2(*(const float2*)&Ab[(r + 8) * G1_ROWF + 2 * t]);
            a[mt][2] = packh2(*(const float2*)&Ab[r * G1_ROWF + 8 + 2 * t]);
            a[mt][3] = packh2(*(const float2*)&Ab[(r + 8) * G1_ROWF + 8 + 2 * t]);
        }
        #pragma unroll
        for (int nt = 0; nt < 4; nt++) {
            const int n = wn * 32 + nt * 8 + g;
            uint32_t b0 = packh2(*(const float2*)&Wb[n * G1_ROWF + 2 * t]);
            uint32_t b1 = packh2(*(const float2*)&Wb[n * G1_ROWF + 8 + 2 * t]);
            #pragma unroll
            for (int mt = 0; mt < 4; mt++)
                mma_f16(acc[mt][nt], a[mt], b0, b1);
        }
    }

    #pragma unroll
    for (int nt = 0; nt < 4; nt++) {
        const int col = n0 + wn * 32 + nt * 8 + 2 * t;
        const float b0 = bias[col], b1 = bias[col + 1];
        #pragma unroll
        for (int mt = 0; mt < 4; mt++) {
            const long r = m0 + wm * 64 + mt * 16 + g;
            *(__half2*)&C[r * 384 + col] =
                __floats2half2_rn(acc[mt][nt][0] + b0, acc[mt][nt][1] + b1);
            *(__half2*)&C[(r + 8) * 384 + col] =
                __floats2half2_rn(acc[mt][nt][2] + b0, acc[mt][nt][3] + b1);
        }
    }
}

// GEMM1 (qkv, fp16) + fused precomp + proj_w fp16 conversion
__global__ __launch_bounds__(256, 2) void gemm1_precomp_kernel(
    const float* __restrict__ A, const float* __restrict__ W,
    const float* __restrict__ bias, __half* __restrict__ C,
    const float* __restrict__ mask, const float* __restrict__ bias_table,
    const int* __restrict__ rel_index, const float* __restrict__ proj_w)
{
    extern __shared__ float sm[];
    if (blockIdx.y >= M_TILES) {
        const int pid = (blockIdx.y - M_TILES) * 3 + blockIdx.x;
        if (pid < 256) {
            const int wm = pid & 63, h = pid >> 6;
            const float inv_scale = 5.656854249492381f;  // sqrt(32)
            float* dst = g_comb + ((size_t)h * 64 + wm) * 49 * 56;
            for (int q = threadIdx.x; q < 49 * 56; q += 256) {
                int i = q / 56, j = q - i * 56;
                dst[q] = (j < 49)
                    ? (bias_table[rel_index[i * 49 + j] * HEADS + h]
                       + mask[(size_t)wm * (NWIN * NWIN) + i * 49 + j]) * inv_scale
                    : -1e30f;
            }
        } else if (pid < 258) {
            const int base = (pid - 256) * 8192;
            for (int q = threadIdx.x; q < 8192; q += 256)
                g_projw_h[base + q] = __float2half(proj_w[base + q]);
        }
        return;
    }
    gemm_f16cvt_body(A, W, bias, C, sm, (long)blockIdx.y * 128, blockIdx.x * 128);
}

// ---------------------------------------------------------------------------
// GEMM3 fp16 (frozen round-14 winner): out = Ah * Wh^T + bias (fp32 out)
// ---------------------------------------------------------------------------
#define H16_BUFB 6144                            // 128*24*2 bytes per array buf
#define GEMM_H16_SMEM (6 * H16_BUFB)             // 36864

__global__ __launch_bounds__(256, 2) void gemm_h16_kernel(
    const __half* __restrict__ A, const __half* __restrict__ W,
    const float* __restrict__ bias, float* __restrict__ C)
{
    extern __shared__ float smf[];
    __half* sm = (__half*)smf;

    const int tid  = threadIdx.x;
    const int lane = tid & 31;
    const int warp = tid >> 5;
    const int wm   = warp & 1;
    const int wn   = warp >> 1;
    const int g    = lane >> 2;
    const int t    = lane & 3;
    const long m0  = (long)blockIdx.y * 128;

    const int srow = tid >> 1;
    const int sf   = (tid & 1) * 8;
    const __half* gA = A + (m0 + srow) * 128 + sf;
    const __half* gW = W + srow * 128 + sf;
    const uint32_t sbase = (uint32_t)__cvta_generic_to_shared(sm);
    const uint32_t sA = sbase + (srow * 24 + sf) * 2;
    const uint32_t sW = sA + 3 * H16_BUFB;

    auto stage = [&](int kc, int buf) {
        CP_ASYNC16(sA + buf * H16_BUFB, gA + kc * 16);
        CP_ASYNC16(sW + buf * H16_BUFB, gW + kc * 16);
    };

    float acc[4][4][4] = {};

    stage(0, 0); CP_COMMIT();
    stage(1, 1); CP_COMMIT();

    #pragma unroll
    for (int kc = 0; kc < 8; kc++) {
        if (kc < 7) asm volatile("cp.async.wait_group 1;");
        else        asm volatile("cp.async.wait_group 0;");
        __syncthreads();
        if (kc < 6) { stage(kc + 2, (kc + 2) % 3); CP_COMMIT(); }

        const uint32_t* Aw = (const uint32_t*)(sm + (kc % 3) * 128 * 24);
        const uint32_t* Ww = Aw + 3 * (128 * 24 / 2);

        uint32_t a[4][4];
        #pragma unroll
        for (int mt = 0; mt < 4; mt++) {
            const int r = wm * 64 + mt * 16 + g;
            a[mt][0] = Aw[r * 12 + t];
            a[mt][1] = Aw[(r + 8) * 12 + t];
            a[mt][2] = Aw[r * 12 + 4 + t];
            a[mt][3] = Aw[(r + 8) * 12 + 4 + t];
        }
        #pragma unroll
        for (int nt = 0; nt < 4; nt++) {
            const int n = wn * 32 + nt * 8 + g;
            uint32_t b0 = Ww[n * 12 + t];
            uint32_t b1 = Ww[n * 12 + 4 + t];
            #pragma unroll
            for (int mt = 0; mt < 4; mt++)
                mma_f16(acc[mt][nt], a[mt], b0, b1);
        }
    }

    #pragma unroll
    for (int nt = 0; nt < 4; nt++) {
        const int col = wn * 32 + nt * 8 + 2 * t;
        const float b0 = bias[col], b1 = bias[col + 1];
        #pragma unroll
        for (int mt = 0; mt < 4; mt++) {
            const long r = m0 + wm * 64 + mt * 16 + g;
            *(float2*)&C[r * DIMC + col] =
                make_float2(acc[mt][nt][0] + b0, acc[mt][nt][1] + b1);
            *(float2*)&C[(r + 8) * DIMC + col] =
                make_float2(acc[mt][nt][2] + b0, acc[mt][nt][3] + b1);
        }
    }
}

// ---------------------------------------------------------------------------
// Attention v5 (frozen round-14 winner, fp16 in/out).
// ---------------------------------------------------------------------------
__global__ __launch_bounds__(128) void attn_tc_kernel(
    const __half* __restrict__ qkv, __half* __restrict__ outp)
{
    __shared__ __half Qs[64][40];
    __shared__ __half Ks[56][40];
    __shared__ __half Vs[64][40];
    __shared__ __half Ps[64][72];

    const int tid  = threadIdx.x;
    const int lane = tid & 31;
    const int warp = tid >> 5;
    const int g = lane >> 2, t = lane & 3;
    const int b = blockIdx.x >> 2, h = blockIdx.x & 3;
    const float scale = 0.17677669529663687f;   // 32^-0.5

    {
        const __half* base = qkv + ((size_t)b * 49) * 384 + h * 32;
        const uint32_t sQ = (uint32_t)__cvta_generic_to_shared(&Qs[0][0]);
        const uint32_t sK = (uint32_t)__cvta_generic_to_shared(&Ks[0][0]);
        const uint32_t sV = (uint32_t)__cvta_generic_to_shared(&Vs[0][0]);
        for (int q = tid; q < 196; q += 128) {
            int i = q >> 2, seg = q & 3;
            CP_ASYNC16(sQ + i * 80 + seg * 16, base + (size_t)i * 384 + seg * 8);
        }
        for (int q = tid; q < 196; q += 128) {
            int i = q >> 2, seg = q & 3;
            CP_ASYNC16(sK + i * 80 + seg * 16, base + (size_t)i * 384 + 128 + seg * 8);
        }
        for (int q = tid; q < 196; q += 128) {
            int i = q >> 2, seg = q & 3;
            CP_ASYNC16(sV + i * 80 + seg * 16, base + (size_t)i * 384 + 256 + seg * 8);
        }
        CP_COMMIT();
        uint32_t* Kw = (uint32_t*)&Ks[49][0];
        for (int q = tid; q < 140; q += 128) Kw[q] = 0u;
        uint32_t* Vw = (uint32_t*)&Vs[49][0];
        for (int q = tid; q < 300; q += 128) Vw[q] = 0u;
    }

    const int r0 = warp * 16 + g;
    const float* comb = g_comb + ((size_t)h * 64 + (b & 63)) * 49 * 56;
    float c[7][4];
    #pragma unroll
    for (int nt = 0; nt < 7; nt++) {
        const int col = nt * 8 + 2 * t;
        if (r0 < 49) {
            float2 f = *(const float2*)&comb[r0 * 56 + col];
            c[nt][0] = f.x; c[nt][1] = f.y;
        } else { c[nt][0] = 0.f; c[nt][1] = 0.f; }
        if (r0 + 8 < 49) {
            float2 f = *(const float2*)&comb[(r0 + 8) * 56 + col];
            c[nt][2] = f.x; c[nt][3] = f.y;
        } else { c[nt][2] = 0.f; c[nt][3] = 0.f; }
    }

    asm volatile("cp.async.wait_group 0;");
    __syncthreads();

    #pragma unroll
    for (int s = 0; s < 2; s++) {
        const int k0 = s * 16;
        uint32_t a[4];
        a[0] = *(const uint32_t*)&Qs[r0][k0 + 2 * t];
        a[1] = *(const uint32_t*)&Qs[r0 + 8][k0 + 2 * t];
        a[2] = *(const uint32_t*)&Qs[r0][k0 + 8 + 2 * t];
        a[3] = *(const uint32_t*)&Qs[r0 + 8][k0 + 8 + 2 * t];
        #pragma unroll
        for (int nt = 0; nt < 7; nt++) {
            const int n = nt * 8 + g;
            uint32_t b0 = *(const uint32_t*)&Ks[n][k0 + 2 * t];
            uint32_t b1 = *(const uint32_t*)&Ks[n][k0 + 8 + 2 * t];
            mma_f16(c[nt], a, b0, b1);
        }
    }

    {
        float mx0 = -1e30f, mx1 = -1e30f;
        #pragma unroll
        for (int nt = 0; nt < 7; nt++) {
            mx0 = fmaxf(mx0, fmaxf(c[nt][0], c[nt][1]));
            mx1 = fmaxf(mx1, fmaxf(c[nt][2], c[nt][3]));
        }
        mx0 = fmaxf(mx0, __shfl_xor_sync(0xffffffffu, mx0, 1));
        mx0 = fmaxf(mx0, __shfl_xor_sync(0xffffffffu, mx0, 2));
        mx1 = fmaxf(mx1, __shfl_xor_sync(0xffffffffu, mx1, 1));
        mx1 = fmaxf(mx1, __shfl_xor_sync(0xffffffffu, mx1, 2));
        float s0 = 0.f, s1 = 0.f;
        #pragma unroll
        for (int nt = 0; nt < 7; nt++) {
            c[nt][0] = __expf((c[nt][0] - mx0) * scale);
            c[nt][1] = __expf((c[nt][1] - mx0) * scale);
            c[nt][2] = __expf((c[nt][2] - mx1) * scale);
            c[nt][3] = __expf((c[nt][3] - mx1) * scale);
            s0 += c[nt][0] + c[nt][1];
            s1 += c[nt][2] + c[nt][3];
        }
        s0 += __shfl_xor_sync(0xffffffffu, s0, 1);
        s0 += __shfl_xor_sync(0xffffffffu, s0, 2);
        s1 += __shfl_xor_sync(0xffffffffu, s1, 1);
        s1 += __shfl_xor_sync(0xffffffffu, s1, 2);
        const float i0 = 1.f / s0, i1 = 1.f / s1;

        #pragma unroll
        for (int nt = 0; nt < 7; nt++) {
            const int col = nt * 8 + 2 * t;
            *(__half2*)&Ps[r0][col] =
                __floats2half2_rn(c[nt][0] * i0, c[nt][1] * i0);
            *(__half2*)&Ps[r0 + 8][col] =
                __floats2half2_rn(c[nt][2] * i1, c[nt][3] * i1);
        }
        *(__half2*)&Ps[r0][56 + 2 * t]     = __floats2half2_rn(0.f, 0.f);
        *(__half2*)&Ps[r0 + 8][56 + 2 * t] = __floats2half2_rn(0.f, 0.f);
    }
    __syncwarp();

    float o[4][4];
    #pragma unroll
    for (int nt = 0; nt < 4; nt++)
        #pragma unroll
        for (int e = 0; e < 4; e++) o[nt][e] = 0.f;

    #pragma unroll
    for (int s = 0; s < 4; s++) {
        const int k0 = s * 16;
        uint32_t a[4];
        a[0] = *(const uint32_t*)&Ps[r0][k0 + 2 * t];
        a[1] = *(const uint32_t*)&Ps[r0 + 8][k0 + 2 * t];
        a[2] = *(const uint32_t*)&Ps[r0][k0 + 8 + 2 * t];
        a[3] = *(const uint32_t*)&Ps[r0 + 8][k0 + 8 + 2 * t];
        #pragma unroll
        for (int nt = 0; nt < 4; nt++) {
            const int n = nt * 8 + g;
            uint32_t b0 = (uint32_t)*(const unsigned short*)&Vs[k0 + 2 * t][n]
                        | ((uint32_t)*(const unsigned short*)&Vs[k0 + 2 * t + 1][n] << 16);
            uint32_t b1 = (uint32_t)*(const unsigned short*)&Vs[k0 + 8 + 2 * t][n]
                        | ((uint32_t)*(const unsigned short*)&Vs[k0 + 9 + 2 * t][n] << 16);
            mma_f16(o[nt], a, b0, b1);
        }
    }

    #pragma unroll
    for (int nt = 0; nt < 4; nt++) {
        const int d = nt * 8 + 2 * t;
        if (r0 < 49)
            *(__half2*)&outp[((size_t)b * 49 + r0) * DIMC + h * HD + d]
                = __floats2half2_rn(o[nt][0], o[nt][1]);
        if (r0 + 8 < 49)
            *(__half2*)&outp[((size_t)b * 49 + r0 + 8) * DIMC + h * HD + d]
                = __floats2half2_rn(o[nt][2], o[nt][3]);
    }
}

// ---------------------------------------------------------------------------
extern "C" void kernel_launch(void* const* d_in, const int* in_sizes, int n_in,
                              void* d_out, int out_size)
{
    const float* x          = (const float*)d_in[0];
    const float* mask       = (const float*)d_in[1];
    const float* qkv_w      = (const float*)d_in[2];
    const float* qkv_b      = (const float*)d_in[3];
    const float* proj_w     = (const float*)d_in[4];
    const float* proj_b     = (const float*)d_in[5];
    const float* bias_table = (const float*)d_in[6];
    const int*   rel_index  = (const int*)d_in[7];
    float*       out        = (float*)d_out;

    __half *qkvbuf = nullptr, *attbuf = nullptr, *pwbuf = nullptr;
    cudaGetSymbolAddress((void**)&qkvbuf, g_qkv_h);
    cudaGetSymbolAddress((void**)&attbuf, g_att_h);
    cudaGetSymbolAddress((void**)&pwbuf, g_projw_h);

    cudaFuncSetAttribute(gemm1_precomp_kernel,
                         cudaFuncAttributeMaxDynamicSharedMemorySize, GEMM_SMEM_BYTES);
    cudaFuncSetAttribute(gemm_h16_kernel,
                         cudaFuncAttributeMaxDynamicSharedMemorySize, GEMM_H16_SMEM);

    dim3 g1(384 / 128, M_TILES + 86);
    gemm1_precomp_kernel<<<g1, 256, GEMM_SMEM_BYTES>>>(
        x, qkv_w, qkv_b, qkvbuf, mask, bias_table, rel_index, proj_w);

    attn_tc_kernel<<<NB * HEADS, 128>>>(qkvbuf, attbuf);

    dim3 g3(1, M_TILES);
    gemm_h16_kernel<<<g3, 256, GEMM_H16_SMEM>>>(attbuf, pwbuf, proj_b, out);
}

// round 16
// speedup vs baseline: 1.6591x; 1.0771x over previous
#include <cuda_runtime.h>
#include <cuda_fp16.h>
#include <math.h>
#include <stdint.h>

// Problem constants
#define DIMC   128
#define NWIN   49
#define HEADS  4
#define HD     32
#define NB     4096
#define M_TOTAL (NB * NWIN)        // 200704 = 1568 * 128
#define M_TILES (M_TOTAL / 128)    // 1568

// Scratch (allocation-free rule: static device globals)
__device__ __half g_qkv_h[(size_t)NB * NWIN * 384]; // [M, 384] fp16 q|k|v
__device__ __half g_att_h[(size_t)NB * NWIN * DIMC];// [M, 128] fp16 attn out
__device__ __half g_projw_h[DIMC * DIMC];           // fp16 proj_w
__device__ float  g_comb[4 * 64 * 49 * 56];         // (bias+mask)*sqrt(hd)

__device__ __forceinline__ void mma_f16(float c[4], const uint32_t a[4],
                                        uint32_t b0, uint32_t b1) {
    asm volatile(
        "mma.sync.aligned.m16n8k16.row.col.f32.f16.f16.f32 "
        "{%0,%1,%2,%3}, {%4,%5,%6,%7}, {%8,%9}, {%0,%1,%2,%3};"
        : "+f"(c[0]), "+f"(c[1]), "+f"(c[2]), "+f"(c[3])
        : "r"(a[0]), "r"(a[1]), "r"(a[2]), "r"(a[3]), "r"(b0), "r"(b1));
}

__device__ __forceinline__ uint32_t packh2(float2 f) {
    __half2 h = __floats2half2_rn(f.x, f.y);   // low = f.x (k even), high = f.y
    return *(uint32_t*)&h;
}

#define CP_ASYNC16(dst, src) \
    asm volatile("cp.async.ca.shared.global [%0], [%1], 16;" :: "r"(dst), "l"(src))
#define CP_COMMIT() asm volatile("cp.async.commit_group;")

// ---------------------------------------------------------------------------
// GEMM1 v7 (frozen round-15 winner): fp16 tensor cores with
// convert-at-fragment-load. C[M][384] = A[M][128]*W[384][128]^T + bias (fp16).
// ---------------------------------------------------------------------------
#define G1_ROWF   24
#define G1_BUFB   (128 * G1_ROWF * 4)            // 12288 B per array buf
#define GEMM_SMEM_BYTES (6 * G1_BUFB)            // 73728

__device__ __forceinline__ void gemm_f16cvt_body(
    const float* __restrict__ A, const float* __restrict__ W,
    const float* __restrict__ bias, __half* __restrict__ C,
    float* sm, long m0, int n0)
{
    const int tid  = threadIdx.x;
    const int lane = tid & 31;
    const int warp = tid >> 5;
    const int wm   = warp & 1;
    const int wn   = warp >> 1;
    const int g    = lane >> 2;
    const int t    = lane & 3;

    const int srow = tid >> 2;
    const int sf   = tid & 3;
    const float* gA = A + (m0 + srow) * 128 + sf * 4;
    const float* gW = W + ((size_t)n0 + srow) * 128 + sf * 4;
    const uint32_t sbase = (uint32_t)__cvta_generic_to_shared(sm);
    const uint32_t sA = sbase + (srow * G1_ROWF + sf * 4) * 4;
    const uint32_t sW = sA + 3 * G1_BUFB;
    const uint32_t ROW64 = 64 * G1_ROWF * 4;

    auto stage = [&](int kc, int buf) {
        const float* a = gA + kc * 16;
        const float* w = gW + kc * 16;
        CP_ASYNC16(sA + buf * G1_BUFB,         a);
        CP_ASYNC16(sA + buf * G1_BUFB + ROW64, a + 64 * 128);
        CP_ASYNC16(sW + buf * G1_BUFB,         w);
        CP_ASYNC16(sW + buf * G1_BUFB + ROW64, w + 64 * 128);
    };

    float acc[4][4][4] = {};

    stage(0, 0); CP_COMMIT();
    stage(1, 1); CP_COMMIT();

    #pragma unroll
    for (int kc = 0; kc < 8; kc++) {
        if (kc < 7) asm volatile("cp.async.wait_group 1;");
        else        asm volatile("cp.async.wait_group 0;");
        __syncthreads();
        if (kc < 6) { stage(kc + 2, (kc + 2) % 3); CP_COMMIT(); }

        const float* Ab = sm + (kc % 3) * (128 * G1_ROWF);
        const float* Wb = Ab + 3 * (128 * G1_ROWF);

        uint32_t a[4][4];
        #pragma unroll
        for (int mt = 0; mt < 4; mt++) {
            const int r = wm * 64 + mt * 16 + g;
            a[mt][0] = packh2(*(const float2*)&Ab[r * G1_ROWF + 2 * t]);
            a[mt][1] = packh2(*(const float2*)&Ab[(r + 8) * G1_ROWF + 2 * t]);
            a[mt][2] = packh2(*(const float2*)&Ab[r * G1_ROWF + 8 + 2 * t]);
            a[mt][3] = packh2(*(const float2*)&Ab[(r + 8) * G1_ROWF + 8 + 2 * t]);
        }
        #pragma unroll
        for (int nt = 0; nt < 4; nt++) {
            const int n = wn * 32 + nt * 8 + g;
            uint32_t b0 = packh2(*(const float2*)&Wb[n * G1_ROWF + 2 * t]);
            uint32_t b1 = packh2(*(const float2*)&Wb[n * G1_ROWF + 8 + 2 * t]);
            #pragma unroll
            for (int mt = 0; mt < 4; mt++)
                mma_f16(acc[mt][nt], a[mt], b0, b1);
        }
    }

    #pragma unroll
    for (int nt = 0; nt < 4; nt++) {
        const int col = n0 + wn * 32 + nt * 8 + 2 * t;
        const float b0 = bias[col], b1 = bias[col + 1];
        #pragma unroll
        for (int mt = 0; mt < 4; mt++) {
            const long r = m0 + wm * 64 + mt * 16 + g;
            *(__half2*)&C[r * 384 + col] =
                __floats2half2_rn(acc[mt][nt][0] + b0, acc[mt][nt][1] + b1);
            *(__half2*)&C[(r + 8) * 384 + col] =
                __floats2half2_rn(acc[mt][nt][2] + b0, acc[mt][nt][3] + b1);
        }
    }
}

// GEMM1 (qkv, fp16) + fused precomp + proj_w fp16 conversion
__global__ __launch_bounds__(256, 2) void gemm1_precomp_kernel(
    const float* __restrict__ A, const float* __restrict__ W,
    const float* __restrict__ bias, __half* __restrict__ C,
    const float* __restrict__ mask, const float* __restrict__ bias_table,
    const int* __restrict__ rel_index, const float* __restrict__ proj_w)
{
    extern __shared__ float sm[];
    if (blockIdx.y >= M_TILES) {
        const int pid = (blockIdx.y - M_TILES) * 3 + blockIdx.x;
        if (pid < 256) {
            const int wm = pid & 63, h = pid >> 6;
            const float inv_scale = 5.656854249492381f;  // sqrt(32)
            float* dst = g_comb + ((size_t)h * 64 + wm) * 49 * 56;
            for (int q = threadIdx.x; q < 49 * 56; q += 256) {
                int i = q / 56, j = q - i * 56;
                dst[q] = (j < 49)
                    ? (bias_table[rel_index[i * 49 + j] * HEADS + h]
                       + mask[(size_t)wm * (NWIN * NWIN) + i * 49 + j]) * inv_scale
                    : -1e30f;
            }
        } else if (pid < 258) {
            const int base = (pid - 256) * 8192;
            for (int q = threadIdx.x; q < 8192; q += 256)
                g_projw_h[base + q] = __float2half(proj_w[base + q]);
        }
        return;
    }
    gemm_f16cvt_body(A, W, bias, C, sm, (long)blockIdx.y * 128, blockIdx.x * 128);
}

// ---------------------------------------------------------------------------
// GEMM3 fp16 (frozen round-14 winner): out = Ah * Wh^T + bias (fp32 out)
// ---------------------------------------------------------------------------
#define H16_BUFB 6144                            // 128*24*2 bytes per array buf
#define GEMM_H16_SMEM (6 * H16_BUFB)             // 36864

__global__ __launch_bounds__(256, 2) void gemm_h16_kernel(
    const __half* __restrict__ A, const __half* __restrict__ W,
    const float* __restrict__ bias, float* __restrict__ C)
{
    extern __shared__ float smf[];
    __half* sm = (__half*)smf;

    const int tid  = threadIdx.x;
    const int lane = tid & 31;
    const int warp = tid >> 5;
    const int wm   = warp & 1;
    const int wn   = warp >> 1;
    const int g    = lane >> 2;
    const int t    = lane & 3;
    const long m0  = (long)blockIdx.y * 128;

    const int srow = tid >> 1;
    const int sf   = (tid & 1) * 8;
    const __half* gA = A + (m0 + srow) * 128 + sf;
    const __half* gW = W + srow * 128 + sf;
    const uint32_t sbase = (uint32_t)__cvta_generic_to_shared(sm);
    const uint32_t sA = sbase + (srow * 24 + sf) * 2;
    const uint32_t sW = sA + 3 * H16_BUFB;

    auto stage = [&](int kc, int buf) {
        CP_ASYNC16(sA + buf * H16_BUFB, gA + kc * 16);
        CP_ASYNC16(sW + buf * H16_BUFB, gW + kc * 16);
    };

    float acc[4][4][4] = {};

    stage(0, 0); CP_COMMIT();
    stage(1, 1); CP_COMMIT();

    #pragma unroll
    for (int kc = 0; kc < 8; kc++) {
        if (kc < 7) asm volatile("cp.async.wait_group 1;");
        else        asm volatile("cp.async.wait_group 0;");
        __syncthreads();
        if (kc < 6) { stage(kc + 2, (kc + 2) % 3); CP_COMMIT(); }

        const uint32_t* Aw = (const uint32_t*)(sm + (kc % 3) * 128 * 24);
        const uint32_t* Ww = Aw + 3 * (128 * 24 / 2);

        uint32_t a[4][4];
        #pragma unroll
        for (int mt = 0; mt < 4; mt++) {
            const int r = wm * 64 + mt * 16 + g;
            a[mt][0] = Aw[r * 12 + t];
            a[mt][1] = Aw[(r + 8) * 12 + t];
            a[mt][2] = Aw[r * 12 + 4 + t];
            a[mt][3] = Aw[(r + 8) * 12 + 4 + t];
        }
        #pragma unroll
        for (int nt = 0; nt < 4; nt++) {
            const int n = wn * 32 + nt * 8 + g;
            uint32_t b0 = Ww[n * 12 + t];
            uint32_t b1 = Ww[n * 12 + 4 + t];
            #pragma unroll
            for (int mt = 0; mt < 4; mt++)
                mma_f16(acc[mt][nt], a[mt], b0, b1);
        }
    }

    #pragma unroll
    for (int nt = 0; nt < 4; nt++) {
        const int col = wn * 32 + nt * 8 + 2 * t;
        const float b0 = bias[col], b1 = bias[col + 1];
        #pragma unroll
        for (int mt = 0; mt < 4; mt++) {
            const long r = m0 + wm * 64 + mt * 16 + g;
            *(float2*)&C[r * DIMC + col] =
                make_float2(acc[mt][nt][0] + b0, acc[mt][nt][1] + b1);
            *(float2*)&C[(r + 8) * DIMC + col] =
                make_float2(acc[mt][nt][2] + b0, acc[mt][nt][3] + b1);
        }
    }
}

// ---------------------------------------------------------------------------
// Attention v6: P stays entirely in registers. The QK accumulator fragment
// (c0,c1 = row r0 cols 2t,2t+1; c2,c3 = row r0+8) is exactly the m16n8k16
// A-fragment layout for PV: for k-step s, a = {pack(c[2s][0],c[2s][1]),
// pack(c[2s][2],c[2s][3]), pack(c[2s+1][0..1]), pack(c[2s+1][2..3])}
// (nt=7 -> zeros). Deletes the Ps smem array, 28 STS + 16 LDS per warp,
// pad zeroing and the __syncwarp. Rounding identical (__floats2half2_rn of
// the same c*inv values).
// ---------------------------------------------------------------------------
__global__ __launch_bounds__(128) void attn_tc_kernel(
    const __half* __restrict__ qkv, __half* __restrict__ outp)
{
    __shared__ __half Qs[64][40];
    __shared__ __half Ks[56][40];
    __shared__ __half Vs[64][40];

    const int tid  = threadIdx.x;
    const int lane = tid & 31;
    const int warp = tid >> 5;
    const int g = lane >> 2, t = lane & 3;
    const int b = blockIdx.x >> 2, h = blockIdx.x & 3;
    const float scale = 0.17677669529663687f;   // 32^-0.5

    {
        const __half* base = qkv + ((size_t)b * 49) * 384 + h * 32;
        const uint32_t sQ = (uint32_t)__cvta_generic_to_shared(&Qs[0][0]);
        const uint32_t sK = (uint32_t)__cvta_generic_to_shared(&Ks[0][0]);
        const uint32_t sV = (uint32_t)__cvta_generic_to_shared(&Vs[0][0]);
        for (int q = tid; q < 196; q += 128) {
            int i = q >> 2, seg = q & 3;
            CP_ASYNC16(sQ + i * 80 + seg * 16, base + (size_t)i * 384 + seg * 8);
        }
        for (int q = tid; q < 196; q += 128) {
            int i = q >> 2, seg = q & 3;
            CP_ASYNC16(sK + i * 80 + seg * 16, base + (size_t)i * 384 + 128 + seg * 8);
        }
        for (int q = tid; q < 196; q += 128) {
            int i = q >> 2, seg = q & 3;
            CP_ASYNC16(sV + i * 80 + seg * 16, base + (size_t)i * 384 + 256 + seg * 8);
        }
        CP_COMMIT();
        uint32_t* Kw = (uint32_t*)&Ks[49][0];
        for (int q = tid; q < 140; q += 128) Kw[q] = 0u;
        uint32_t* Vw = (uint32_t*)&Vs[49][0];
        for (int q = tid; q < 300; q += 128) Vw[q] = 0u;
    }

    const int r0 = warp * 16 + g;
    const float* comb = g_comb + ((size_t)h * 64 + (b & 63)) * 49 * 56;
    float c[7][4];
    #pragma unroll
    for (int nt = 0; nt < 7; nt++) {
        const int col = nt * 8 + 2 * t;
        if (r0 < 49) {
            float2 f = *(const float2*)&comb[r0 * 56 + col];
            c[nt][0] = f.x; c[nt][1] = f.y;
        } else { c[nt][0] = 0.f; c[nt][1] = 0.f; }
        if (r0 + 8 < 49) {
            float2 f = *(const float2*)&comb[(r0 + 8) * 56 + col];
            c[nt][2] = f.x; c[nt][3] = f.y;
        } else { c[nt][2] = 0.f; c[nt][3] = 0.f; }
    }

    asm volatile("cp.async.wait_group 0;");
    __syncthreads();

    // ---- S' = QK^T + comb*sqrt(hd)  (2 x m16n8k16 k-steps) ----
    #pragma unroll
    for (int s = 0; s < 2; s++) {
        const int k0 = s * 16;
        uint32_t a[4];
        a[0] = *(const uint32_t*)&Qs[r0][k0 + 2 * t];
        a[1] = *(const uint32_t*)&Qs[r0 + 8][k0 + 2 * t];
        a[2] = *(const uint32_t*)&Qs[r0][k0 + 8 + 2 * t];
        a[3] = *(const uint32_t*)&Qs[r0 + 8][k0 + 8 + 2 * t];
        #pragma unroll
        for (int nt = 0; nt < 7; nt++) {
            const int n = nt * 8 + g;
            uint32_t b0 = *(const uint32_t*)&Ks[n][k0 + 2 * t];
            uint32_t b1 = *(const uint32_t*)&Ks[n][k0 + 8 + 2 * t];
            mma_f16(c[nt], a, b0, b1);
        }
    }

    // ---- softmax(scale * S') in registers; P kept in registers ----
    {
        float mx0 = -1e30f, mx1 = -1e30f;
        #pragma unroll
        for (int nt = 0; nt < 7; nt++) {
            mx0 = fmaxf(mx0, fmaxf(c[nt][0], c[nt][1]));
            mx1 = fmaxf(mx1, fmaxf(c[nt][2], c[nt][3]));
        }
        mx0 = fmaxf(mx0, __shfl_xor_sync(0xffffffffu, mx0, 1));
        mx0 = fmaxf(mx0, __shfl_xor_sync(0xffffffffu, mx0, 2));
        mx1 = fmaxf(mx1, __shfl_xor_sync(0xffffffffu, mx1, 1));
        mx1 = fmaxf(mx1, __shfl_xor_sync(0xffffffffu, mx1, 2));
        float s0 = 0.f, s1 = 0.f;
        #pragma unroll
        for (int nt = 0; nt < 7; nt++) {
            c[nt][0] = __expf((c[nt][0] - mx0) * scale);
            c[nt][1] = __expf((c[nt][1] - mx0) * scale);
            c[nt][2] = __expf((c[nt][2] - mx1) * scale);
            c[nt][3] = __expf((c[nt][3] - mx1) * scale);
            s0 += c[nt][0] + c[nt][1];
            s1 += c[nt][2] + c[nt][3];
        }
        s0 += __shfl_xor_sync(0xffffffffu, s0, 1);
        s0 += __shfl_xor_sync(0xffffffffu, s0, 2);
        s1 += __shfl_xor_sync(0xffffffffu, s1, 1);
        s1 += __shfl_xor_sync(0xffffffffu, s1, 2);
        const float i0 = 1.f / s0, i1 = 1.f / s1;
        #pragma unroll
        for (int nt = 0; nt < 7; nt++) {
            c[nt][0] *= i0; c[nt][1] *= i0;
            c[nt][2] *= i1; c[nt][3] *= i1;
        }
    }

    // ---- O = P V: A-fragments packed straight from the accumulators ----
    float o[4][4];
    #pragma unroll
    for (int nt = 0; nt < 4; nt++)
        #pragma unroll
        for (int e = 0; e < 4; e++) o[nt][e] = 0.f;

    #pragma unroll
    for (int s = 0; s < 4; s++) {
        const int k0 = s * 16;
        uint32_t a[4];
        a[0] = packh2(make_float2(c[2 * s][0], c[2 * s][1]));
        a[1] = packh2(make_float2(c[2 * s][2], c[2 * s][3]));
        if (2 * s + 1 < 7) {
            a[2] = packh2(make_float2(c[2 * s + 1][0], c[2 * s + 1][1]));
            a[3] = packh2(make_float2(c[2 * s + 1][2], c[2 * s + 1][3]));
        } else {
            a[2] = 0u; a[3] = 0u;
        }
        #pragma unroll
        for (int nt = 0; nt < 4; nt++) {
            const int n = nt * 8 + g;
            uint32_t b0 = (uint32_t)*(const unsigned short*)&Vs[k0 + 2 * t][n]
                        | ((uint32_t)*(const unsigned short*)&Vs[k0 + 2 * t + 1][n] << 16);
            uint32_t b1 = (uint32_t)*(const unsigned short*)&Vs[k0 + 8 + 2 * t][n]
                        | ((uint32_t)*(const unsigned short*)&Vs[k0 + 9 + 2 * t][n] << 16);
            mma_f16(o[nt], a, b0, b1);
        }
    }

    #pragma unroll
    for (int nt = 0; nt < 4; nt++) {
        const int d = nt * 8 + 2 * t;
        if (r0 < 49)
            *(__half2*)&outp[((size_t)b * 49 + r0) * DIMC + h * HD + d]
                = __floats2half2_rn(o[nt][0], o[nt][1]);
        if (r0 + 8 < 49)
            *(__half2*)&outp[((size_t)b * 49 + r0 + 8) * DIMC + h * HD + d]
                = __floats2half2_rn(o[nt][2], o[nt][3]);
    }
}

// ---------------------------------------------------------------------------
extern "C" void kernel_launch(void* const* d_in, const int* in_sizes, int n_in,
                              void* d_out, int out_size)
{
    const float* x          = (const float*)d_in[0];
    const float* mask       = (const float*)d_in[1];
    const float* qkv_w      = (const float*)d_in[2];
    const float* qkv_b      = (const float*)d_in[3];
    const float* proj_w     = (const float*)d_in[4];
    const float* proj_b     = (const float*)d_in[5];
    const float* bias_table = (const float*)d_in[6];
    const int*   rel_index  = (const int*)d_in[7];
    float*       out        = (float*)d_out;

    __half *qkvbuf = nullptr, *attbuf = nullptr, *pwbuf = nullptr;
    cudaGetSymbolAddress((void**)&qkvbuf, g_qkv_h);
    cudaGetSymbolAddress((void**)&attbuf, g_att_h);
    cudaGetSymbolAddress((void**)&pwbuf, g_projw_h);

    cudaFuncSetAttribute(gemm1_precomp_kernel,
                         cudaFuncAttributeMaxDynamicSharedMemorySize, GEMM_SMEM_BYTES);
    cudaFuncSetAttribute(gemm_h16_kernel,
                         cudaFuncAttributeMaxDynamicSharedMemorySize, GEMM_H16_SMEM);

    dim3 g1(384 / 128, M_TILES + 86);
    gemm1_precomp_kernel<<<g1, 256, GEMM_SMEM_BYTES>>>(
        x, qkv_w, qkv_b, qkvbuf, mask, bias_table, rel_index, proj_w);

    attn_tc_kernel<<<NB * HEADS, 128>>>(qkvbuf, attbuf);

    dim3 g3(1, M_TILES);
    gemm_h16_kernel<<<g3, 256, GEMM_H16_SMEM>>>(attbuf, pwbuf, proj_b, out);
}